// round 14
// baseline (speedup 1.0000x reference)
#include <cuda_runtime.h>
#include <cuda_fp16.h>
#include <cstdint>

#define BB 32
#define NN 16384
#define CC 256
#define DD 64
#define SS 7
#define HH 128
#define MROWS (BB*NN)
#define SCALE_ATTN 0.125f
#define EPS_ATTN 1e-6f
#define LN_EPS 1e-5f
#define NCHUNK 32
#define CHUNK (NN/NCHUNK)
#define PART_STRIDE 456
#define APITCH 40   // fp16 row pitch (80B: 16B-aligned rows, conflict-free ldmatrix)

// proj smem (dynamic): two chunk buffers of [Ah|Bh] (each 128x40 fp16), then params
#define PJ_B      10240
#define PJ_BUF    20480
#define PJ_PARAMS 40960     // s_mean[128], s_rstd[128], sG[128], sT[128]
#define PJ_SMEM   43008

// ---------------- scratch (static device globals; no allocation) ----------------
__device__ float g_K[MROWS*DD];
__device__ float g_V[MROWS*DD];
__device__ float g_q[BB*SS*DD];
__device__ float g_part[BB*NCHUNK*PART_STRIDE];
__device__ __half g_WbH[128*256];   // fp16 g-scaled weights, row-major [n][c]
__device__ float g_Gn[128];         // G_n = sum_c g_c W_cn
__device__ float g_Tn[128];         // T_n = sum_c b_c W_cn

__device__ __forceinline__ float sigmoidf_(float x) { return 1.0f / (1.0f + __expf(-x)); }

__device__ __forceinline__ uint32_t smem_u32(const void* p) {
    uint32_t a;
    asm("{ .reg .u64 t; cvta.to.shared.u64 t, %1; cvt.u32.u64 %0, t; }" : "=r"(a) : "l"(p));
    return a;
}
__device__ __forceinline__ void mma16816(float* d, const uint32_t* a, const uint32_t* b) {
    asm volatile(
        "mma.sync.aligned.m16n8k16.row.col.f32.f16.f16.f32 "
        "{%0,%1,%2,%3}, {%4,%5,%6,%7}, {%8,%9}, {%0,%1,%2,%3};"
        : "+f"(d[0]), "+f"(d[1]), "+f"(d[2]), "+f"(d[3])
        : "r"(a[0]), "r"(a[1]), "r"(a[2]), "r"(a[3]), "r"(b[0]), "r"(b[1]));
}
__device__ __forceinline__ void ldsm_x4(uint32_t* r, uint32_t addr) {
    asm volatile("ldmatrix.sync.aligned.m8n8.x4.shared.b16 {%0,%1,%2,%3}, [%4];"
        : "=r"(r[0]), "=r"(r[1]), "=r"(r[2]), "=r"(r[3]) : "r"(addr));
}

// ---------------- kernel 0: fused slot init (out = mu) + iteration-0 q projection ----------------
__global__ void __launch_bounds__(256) initq_kernel(
    const float* __restrict__ mu_in, float* __restrict__ out,
    const float* __restrict__ qlg, const float* __restrict__ qlb,
    const float* __restrict__ Wq,
    const float* __restrict__ bqlg, const float* __restrict__ bqlb,
    const float* __restrict__ bWq)
{
    __shared__ float xs[8][64];
    const int tid = threadIdx.x, lane = tid & 31, ws = tid >> 5;
    const int wid = blockIdx.x * 8 + ws;          // 0..223 == b*7+m
    const int m = wid % SS;

    const float* x = mu_in + wid * DD;
    float x0 = x[lane], x1 = x[lane + 32];
    out[wid * DD + lane]      = x0;
    out[wid * DD + lane + 32] = x1;

    float s = x0 + x1, q = x0 * x0 + x1 * x1;
    #pragma unroll
    for (int o = 16; o; o >>= 1) {
        s += __shfl_xor_sync(0xffffffffu, s, o);
        q += __shfl_xor_sync(0xffffffffu, q, o);
    }
    float mu = s * (1.f / 64.f);
    float rs = rsqrtf(q * (1.f / 64.f) - mu * mu + LN_EPS);

    const float* lg = (m < 6) ? qlg : bqlg;
    const float* lb = (m < 6) ? qlb : bqlb;
    const float* W  = (m < 6) ? Wq  : bWq;

    xs[ws][lane]      = (x0 - mu) * rs * lg[lane]      + lb[lane];
    xs[ws][lane + 32] = (x1 - mu) * rs * lg[lane + 32] + lb[lane + 32];
    __syncwarp();

    float q0 = 0.f, q1 = 0.f;
    #pragma unroll
    for (int e = 0; e < 64; e++) {
        float xe = xs[ws][e];
        q0 += xe * W[e * 64 + lane];
        q1 += xe * W[e * 64 + lane + 32];
    }
    g_q[wid * DD + lane]      = q0;
    g_q[wid * DD + lane + 32] = q1;
}

// ---------------- kernel 0b: W' = g*[Wk|Wv]^T -> fp16 [n][c]; plus G/T column sums ----------------
__global__ void wsplit_kernel(const float* __restrict__ Wk, const float* __restrict__ Wv,
                              const float* __restrict__ lng, const float* __restrict__ lnb) {
    int idx = blockIdx.x * 256 + threadIdx.x;
    if (idx < 128 * 256) {
        int n = idx >> 8;
        int c = idx & 255;
        float w = (n < 64) ? Wk[c * 64 + n] : Wv[c * 64 + (n - 64)];
        g_WbH[n * 256 + c] = __float2half_rn(lng[c] * w);
    }
    if (blockIdx.x == 0 && threadIdx.x < 128) {
        int n = threadIdx.x;
        float G = 0.f, T = 0.f;
        #pragma unroll 4
        for (int c = 0; c < 256; c++) {
            float w = (n < 64) ? Wk[c * 64 + n] : Wv[c * 64 + (n - 64)];
            G += lng[c] * w;
            T += lnb[c] * w;
        }
        g_Gn[n] = G;
        g_Tn[n] = T;
    }
}

// ---------------- kernel 1: [K|V] projection on raw fp16 X; LN folded into epilogue ----------------
__global__ void __launch_bounds__(256, 2) proj_mma_kernel(const float* __restrict__ X)
{
    extern __shared__ char smem[];
    float* s_mean = (float*)(smem + PJ_PARAMS);
    float* s_rstd = (float*)(smem + PJ_PARAMS + 512);
    float* sG     = (float*)(smem + PJ_PARAMS + 1024);
    float* sT     = (float*)(smem + PJ_PARAMS + 1536);

    const int tid = threadIdx.x, wid = tid >> 5, lane = tid & 31;
    const int m0 = blockIdx.x * 128;
    const uint32_t sbase = smem_u32(smem);

    if (tid < 128) {
        sG[tid] = g_Gn[tid];
        sT[tid] = g_Tn[tid];
    }

    // loader roles
    const int r   = tid >> 1;
    const int seg = tid & 1;
    const float* xrow = X + (size_t)(m0 + r) * CC + seg * 16;
    const __half* wHrow = g_WbH + r * 256 + seg * 16;

    // mma roles
    const int mw = wid >> 1, nw = wid & 1;
    const int g  = lane >> 2, tg = lane & 3;
    const int mat = lane >> 3, rb = lane & 7;
    const uint32_t aoff = (uint32_t)((mw*32 + rb + (mat & 1)*8) * APITCH + (mat >> 1)*8) * 2;
    const uint32_t boff = (uint32_t)((nw*64 + rb) * APITCH + mat*8) * 2;

    float acc[2][8][4];
    #pragma unroll
    for (int mt = 0; mt < 2; mt++)
        #pragma unroll
        for (int nt = 0; nt < 8; nt++)
            #pragma unroll
            for (int e = 0; e < 4; e++) acc[mt][nt][e] = 0.f;

    float statS = 0.f, statQ = 0.f;   // per-thread LN partials (this thread's 128 cols)
    float4 xv[4];
    uint4 bvh[2];

    // prologue: load chunk0 regs, stage buf0 (+stats), load chunk1 regs
    #pragma unroll
    for (int i = 0; i < 4; i++) xv[i] = *(const float4*)(xrow + i * 4);
    bvh[0] = *(const uint4*)(wHrow);
    bvh[1] = *(const uint4*)(wHrow + 8);

    {   // stage chunk 0 -> buf 0
        char* Ah = smem;
        char* Bh = smem + PJ_B;
        uint32_t pk[8];
        #pragma unroll
        for (int i = 0; i < 4; i++) {
            statS += xv[i].x + xv[i].y + xv[i].z + xv[i].w;
            statQ += xv[i].x*xv[i].x + xv[i].y*xv[i].y + xv[i].z*xv[i].z + xv[i].w*xv[i].w;
            __half2 h01 = __float22half2_rn(make_float2(xv[i].x, xv[i].y));
            __half2 h23 = __float22half2_rn(make_float2(xv[i].z, xv[i].w));
            pk[i * 2]     = *(uint32_t*)&h01;
            pk[i * 2 + 1] = *(uint32_t*)&h23;
        }
        *(uint4*)(Ah + r * 80 + seg * 32)      = make_uint4(pk[0], pk[1], pk[2], pk[3]);
        *(uint4*)(Ah + r * 80 + seg * 32 + 16) = make_uint4(pk[4], pk[5], pk[6], pk[7]);
        *(uint4*)(Bh + r * 80 + seg * 32)      = bvh[0];
        *(uint4*)(Bh + r * 80 + seg * 32 + 16) = bvh[1];
    }
    #pragma unroll
    for (int i = 0; i < 4; i++) xv[i] = *(const float4*)(xrow + 32 + i * 4);
    bvh[0] = *(const uint4*)(wHrow + 32);
    bvh[1] = *(const uint4*)(wHrow + 40);
    __syncthreads();

    #pragma unroll 1
    for (int kc = 0; kc < 8; kc++) {
        const uint32_t bufo = (uint32_t)(kc & 1) * PJ_BUF;

        // ---- stage chunk kc+1 into the other buffer (+stats) ----
        if (kc < 7) {
            uint32_t nb = (uint32_t)((kc + 1) & 1) * PJ_BUF;
            char* Ah = smem + nb;
            char* Bh = smem + nb + PJ_B;
            uint32_t pk[8];
            #pragma unroll
            for (int i = 0; i < 4; i++) {
                statS += xv[i].x + xv[i].y + xv[i].z + xv[i].w;
                statQ += xv[i].x*xv[i].x + xv[i].y*xv[i].y + xv[i].z*xv[i].z + xv[i].w*xv[i].w;
                __half2 h01 = __float22half2_rn(make_float2(xv[i].x, xv[i].y));
                __half2 h23 = __float22half2_rn(make_float2(xv[i].z, xv[i].w));
                pk[i * 2]     = *(uint32_t*)&h01;
                pk[i * 2 + 1] = *(uint32_t*)&h23;
            }
            *(uint4*)(Ah + r * 80 + seg * 32)      = make_uint4(pk[0], pk[1], pk[2], pk[3]);
            *(uint4*)(Ah + r * 80 + seg * 32 + 16) = make_uint4(pk[4], pk[5], pk[6], pk[7]);
            *(uint4*)(Bh + r * 80 + seg * 32)      = bvh[0];
            *(uint4*)(Bh + r * 80 + seg * 32 + 16) = bvh[1];
        }
        // ---- prefetch chunk kc+2 from global ----
        if (kc < 6) {
            const float* xp = xrow + (kc + 2) * 32;
            #pragma unroll
            for (int i = 0; i < 4; i++) xv[i] = *(const float4*)(xp + i * 4);
            const __half* wh = wHrow + (kc + 2) * 32;
            bvh[0] = *(const uint4*)(wh);
            bvh[1] = *(const uint4*)(wh + 8);
        }

        // ---- MMA over current buffer via ldmatrix ----
        {
            const uint32_t aH = sbase + bufo + aoff;
            const uint32_t bH = sbase + bufo + PJ_B + boff;

            uint32_t ah[2][2][4];
            #pragma unroll
            for (int mt = 0; mt < 2; mt++)
                #pragma unroll
                for (int ks = 0; ks < 2; ks++)
                    ldsm_x4(ah[mt][ks], aH + mt * 1280 + ks * 32);
            #pragma unroll
            for (int nt = 0; nt < 8; nt++) {
                uint32_t bh[4];
                ldsm_x4(bh, bH + nt * 640);
                #pragma unroll
                for (int ks = 0; ks < 2; ks++)
                    #pragma unroll
                    for (int mt = 0; mt < 2; mt++)
                        mma16816(acc[mt][nt], ah[mt][ks], &bh[ks * 2]);
            }
        }
        __syncthreads();
    }

    // ---- finalize LN stats: combine the two per-row halves (partner lane) ----
    statS += __shfl_xor_sync(0xffffffffu, statS, 1);
    statQ += __shfl_xor_sync(0xffffffffu, statQ, 1);
    if (seg == 0) {
        float mu = statS * (1.f / 256.f);
        s_mean[r] = mu;
        s_rstd[r] = rsqrtf(statQ * (1.f / 256.f) - mu * mu + LN_EPS);
    }
    __syncthreads();

    // ---- epilogue: y = rs*(acc - mu*G) + T ----
    float* dstbase = nw ? g_V : g_K;
    #pragma unroll
    for (int mt = 0; mt < 2; mt++) {
        int lr = mw * 32 + mt * 16 + g;
        float mu0 = s_mean[lr],     rs0 = s_rstd[lr];
        float mu1 = s_mean[lr + 8], rs1 = s_rstd[lr + 8];
        int row0 = m0 + lr;
        #pragma unroll
        for (int nt = 0; nt < 8; nt++) {
            int col = nw * 64 + nt * 8 + tg * 2;     // global n (for G/T)
            int coll = nt * 8 + tg * 2;              // col within K or V
            float G0 = sG[col], G1 = sG[col + 1];
            float T0 = sT[col], T1 = sT[col + 1];
            *(float2*)(dstbase + (size_t)row0 * DD + coll) =
                make_float2(rs0 * (acc[mt][nt][0] - mu0 * G0) + T0,
                            rs0 * (acc[mt][nt][1] - mu0 * G1) + T1);
            *(float2*)(dstbase + (size_t)(row0 + 8) * DD + coll) =
                make_float2(rs1 * (acc[mt][nt][2] - mu1 * G0) + T0,
                            rs1 * (acc[mt][nt][3] - mu1 * G1) + T1);
        }
    }
}

// ---------------- kernel 3: attention — 32 lanes/row (float2), 4-row ILP, 3 blocks/SM ----------------
__global__ void __launch_bounds__(256, 3) attn_kernel(float* __restrict__ part)
{
    const int b = blockIdx.y;
    const int chunk = blockIdx.x;       // 0..NCHUNK-1, CHUNK = 512
    __shared__ float qs[SS * DD];
    __shared__ float Uw[8][PART_STRIDE];
    const int tid = threadIdx.x;
    for (int i = tid; i < SS * DD; i += 256) qs[i] = g_q[b * SS * DD + i];
    __syncthreads();

    const int lane = tid & 31, warp = tid >> 5;

    // hoist q fragments: lane owns d-slice [lane*2, lane*2+1]
    float2 qreg[SS];
    #pragma unroll
    for (int m = 0; m < SS; m++)
        qreg[m] = ((const float2*)(qs + m * DD))[lane];

    float Up[SS][2];
    #pragma unroll
    for (int m = 0; m < SS; m++) { Up[m][0] = 0.f; Up[m][1] = 0.f; }
    float cs[SS] = {0.f, 0.f, 0.f, 0.f, 0.f, 0.f, 0.f};

    const float* Kb = g_K + (size_t)b * NN * DD;
    const float* Vb = g_V + (size_t)b * NN * DD;
    const int base = chunk * CHUNK + warp * 4;

    #pragma unroll 1
    for (int s = 0; s < CHUNK / 32; s++) {
        int n0 = base + s * 32;
        float2 k2[4], v2[4];
        #pragma unroll
        for (int i = 0; i < 4; i++) {
            k2[i] = __ldcs(((const float2*)(Kb + (size_t)(n0 + i) * DD)) + lane);
            v2[i] = __ldcs(((const float2*)(Vb + (size_t)(n0 + i) * DD)) + lane);
        }
        #pragma unroll
        for (int i = 0; i < 4; i++) {
            float l[SS];
            #pragma unroll
            for (int m = 0; m < SS; m++) {
                float p = k2[i].x * qreg[m].x + k2[i].y * qreg[m].y;
                #pragma unroll
                for (int o = 1; o < 32; o <<= 1)
                    p += __shfl_xor_sync(0xffffffffu, p, o);
                l[m] = p * SCALE_ATTN;
            }
            float mx = l[0];
            #pragma unroll
            for (int m = 1; m < SS; m++) mx = fmaxf(mx, l[m]);
            float se = 0.f;
            #pragma unroll
            for (int m = 0; m < SS; m++) { l[m] = __expf(l[m] - mx); se += l[m]; }
            float inv = 1.0f / se;
            #pragma unroll
            for (int m = 0; m < SS; m++) {
                float a = l[m] * inv + EPS_ATTN;
                cs[m] += a;
                Up[m][0] += a * v2[i].x;
                Up[m][1] += a * v2[i].y;
            }
        }
    }

    // each lane owns distinct d-slice: direct store, no cross-lane reduce
    #pragma unroll
    for (int m = 0; m < SS; m++) {
        Uw[warp][m * DD + lane * 2]     = Up[m][0];
        Uw[warp][m * DD + lane * 2 + 1] = Up[m][1];
    }
    if (lane == 0) {
        #pragma unroll
        for (int m = 0; m < SS; m++) Uw[warp][448 + m] = cs[m];
    }
    __syncthreads();

    float* dst = part + (size_t)(b * NCHUNK + chunk) * PART_STRIDE;
    for (int i = tid; i < 455; i += 256) {
        float acc = Uw[0][i];
        #pragma unroll
        for (int w = 1; w < 8; w++) acc += Uw[w][i];
        dst[i] = acc;
    }
}

// ---------------- kernel 4: slot update + fused next-iter q projection ----------------
__global__ void __launch_bounds__(128) update_kernel(
    float* __restrict__ slots,
    const float* __restrict__ Wih, const float* __restrict__ Whh,
    const float* __restrict__ bih, const float* __restrict__ bhh,
    const float* __restrict__ mlng, const float* __restrict__ mlnb,
    const float* __restrict__ mW1,  const float* __restrict__ mb1,
    const float* __restrict__ mW2,  const float* __restrict__ mb2,
    const float* __restrict__ bmlng, const float* __restrict__ bmlnb,
    const float* __restrict__ bmW1,  const float* __restrict__ bmb1,
    const float* __restrict__ bmW2,  const float* __restrict__ bmb2,
    const float* __restrict__ qlg, const float* __restrict__ qlb,
    const float* __restrict__ Wq,
    const float* __restrict__ bqlg, const float* __restrict__ bqlb,
    const float* __restrict__ bWq)
{
    const int b = blockIdx.y;
    const int s = blockIdx.x;
    const int t = threadIdx.x;

    __shared__ float us[64], hs[64], gi[192], gh[192], hn[64], xn[64], hid[128], fin[64], xq[64];
    __shared__ float red[2], red2[2];

    if (t < 64) {
        float ua = 0.f, ca = 0.f;
        #pragma unroll 1
        for (int c = 0; c < NCHUNK; c++) {
            const float* p = g_part + (size_t)(b * NCHUNK + c) * PART_STRIDE;
            ua += p[s * 64 + t];
            ca += p[448 + s];
        }
        us[t] = ua / ca;
        hs[t] = slots[(b * SS + s) * DD + t];
    }
    __syncthreads();

    for (int idx = t; idx < 384; idx += 128) {
        const bool isI = (idx < 192);
        const int oo = isI ? idx : (idx - 192);
        const float* W  = isI ? Wih : Whh;
        const float* xv = isI ? us : hs;
        float acc = isI ? bih[oo] : bhh[oo];
        #pragma unroll
        for (int e = 0; e < 64; e++) acc += xv[e] * W[oo * 64 + e];
        if (isI) gi[oo] = acc; else gh[oo] = acc;
    }
    __syncthreads();

    if (t < 64) {
        float r = sigmoidf_(gi[t] + gh[t]);
        float z = sigmoidf_(gi[64 + t] + gh[64 + t]);
        float n = tanhf(gi[128 + t] + r * gh[128 + t]);
        hn[t] = (1.0f - z) * n + z * hs[t];
    }
    __syncthreads();

    if (t < 32) {
        float a = hn[t], bv = hn[t + 32];
        float sm = a + bv, sq = a * a + bv * bv;
        #pragma unroll
        for (int o = 16; o; o >>= 1) {
            sm += __shfl_xor_sync(0xffffffffu, sm, o);
            sq += __shfl_xor_sync(0xffffffffu, sq, o);
        }
        if (t == 0) {
            float mu = sm * (1.f / 64.f);
            red[0] = mu;
            red[1] = rsqrtf(sq * (1.f / 64.f) - mu * mu + LN_EPS);
        }
    }
    __syncthreads();

    const float* lg = (s < 6) ? mlng : bmlng;
    const float* lb = (s < 6) ? mlnb : bmlnb;
    const float* W1 = (s < 6) ? mW1 : bmW1;
    const float* b1 = (s < 6) ? mb1 : bmb1;
    const float* W2 = (s < 6) ? mW2 : bmW2;
    const float* b2 = (s < 6) ? mb2 : bmb2;

    if (t < 64) xn[t] = (hn[t] - red[0]) * red[1] * lg[t] + lb[t];
    __syncthreads();

    {
        float h1 = b1[t];
        #pragma unroll
        for (int e = 0; e < 64; e++) h1 += xn[e] * W1[e * HH + t];
        hid[t] = fmaxf(h1, 0.f);
    }
    __syncthreads();

    if (t < 64) {
        float o = b2[t];
        #pragma unroll
        for (int jj = 0; jj < 128; jj++) o += hid[jj] * W2[jj * 64 + t];
        float fv = hn[t] + o;
        slots[(b * SS + s) * DD + t] = fv;
        fin[t] = fv;
    }
    __syncthreads();

    // ---- fused q projection for next iteration ----
    if (t < 32) {
        float a = fin[t], bv = fin[t + 32];
        float sm = a + bv, sq = a * a + bv * bv;
        #pragma unroll
        for (int o = 16; o; o >>= 1) {
            sm += __shfl_xor_sync(0xffffffffu, sm, o);
            sq += __shfl_xor_sync(0xffffffffu, sq, o);
        }
        if (t == 0) {
            float mu = sm * (1.f / 64.f);
            red2[0] = mu;
            red2[1] = rsqrtf(sq * (1.f / 64.f) - mu * mu + LN_EPS);
        }
    }
    __syncthreads();

    const float* qg = (s < 6) ? qlg : bqlg;
    const float* qb = (s < 6) ? qlb : bqlb;
    const float* qW = (s < 6) ? Wq  : bWq;

    if (t < 64) xq[t] = (fin[t] - red2[0]) * red2[1] * qg[t] + qb[t];
    __syncthreads();

    if (t < 64) {
        float qv = 0.f;
        #pragma unroll
        for (int e = 0; e < 64; e++) qv += xq[e] * qW[e * 64 + t];
        g_q[(b * SS + s) * DD + t] = qv;
    }
}

// ---------------- launcher ----------------
extern "C" void kernel_launch(void* const* d_in, const int* in_sizes, int n_in,
                              void* d_out, int out_size) {
    (void)in_sizes; (void)n_in; (void)out_size;
    const float* inputs   = (const float*)d_in[0];
    const float* slots_mu = (const float*)d_in[1];
    const float* ln_in_g  = (const float*)d_in[2];
    const float* ln_in_b  = (const float*)d_in[3];
    const float* Wk       = (const float*)d_in[4];
    const float* Wv       = (const float*)d_in[5];
    const float* q_ln_g   = (const float*)d_in[6];
    const float* q_ln_b   = (const float*)d_in[7];
    const float* Wq       = (const float*)d_in[8];
    const float* bq_ln_g  = (const float*)d_in[9];
    const float* bq_ln_b  = (const float*)d_in[10];
    const float* bWq      = (const float*)d_in[11];
    const float* gWih     = (const float*)d_in[12];
    const float* gWhh     = (const float*)d_in[13];
    const float* gbih     = (const float*)d_in[14];
    const float* gbhh     = (const float*)d_in[15];
    const float* mlng     = (const float*)d_in[16];
    const float* mlnb     = (const float*)d_in[17];
    const float* mW1      = (const float*)d_in[18];
    const float* mb1      = (const float*)d_in[19];
    const float* mW2      = (const float*)d_in[20];
    const float* mb2      = (const float*)d_in[21];
    const float* bmlng    = (const float*)d_in[22];
    const float* bmlnb    = (const float*)d_in[23];
    const float* bmW1     = (const float*)d_in[24];
    const float* bmb1     = (const float*)d_in[25];
    const float* bmW2     = (const float*)d_in[26];
    const float* bmb2     = (const float*)d_in[27];
    float* out = (float*)d_out;

    float* part;
    cudaGetSymbolAddress((void**)&part, g_part);

    cudaFuncSetAttribute(proj_mma_kernel,
                         cudaFuncAttributeMaxDynamicSharedMemorySize, PJ_SMEM);

    // order places attn_kernel at launch index 3 for the ncu fixed-index capture
    initq_kernel<<<28, 256>>>(slots_mu, out, q_ln_g, q_ln_b, Wq, bq_ln_g, bq_ln_b, bWq);
    wsplit_kernel<<<128, 256>>>(Wk, Wv, ln_in_g, ln_in_b);
    proj_mma_kernel<<<MROWS / 128, 256, PJ_SMEM>>>(inputs);

    for (int it = 0; it < 3; it++) {
        attn_kernel<<<dim3(NCHUNK, BB), 256>>>(part);
        update_kernel<<<dim3(SS, BB), 128>>>(out, gWih, gWhh, gbih, gbhh,
                                             mlng, mlnb, mW1, mb1, mW2, mb2,
                                             bmlng, bmlnb, bmW1, bmb1, bmW2, bmb2,
                                             q_ln_g, q_ln_b, Wq, bq_ln_g, bq_ln_b, bWq);
    }
}

// round 15
// speedup vs baseline: 1.1772x; 1.1772x over previous
#include <cuda_runtime.h>
#include <cuda_fp16.h>
#include <cstdint>

#define BB 32
#define NN 16384
#define CC 256
#define DD 64
#define SS 7
#define HH 128
#define MROWS (BB*NN)
#define SCALE_ATTN 0.125f
#define EPS_ATTN 1e-6f
#define LN_EPS 1e-5f
#define NCHUNK 16
#define CHUNK (NN/NCHUNK)
#define PART_STRIDE 456
#define APITCH 40   // fp16 row pitch (80B: 16B-aligned rows, conflict-free ldmatrix)

// proj smem (dynamic): two chunk buffers of [Ah|Bh] (each 128x40 fp16), then params
#define PJ_B      10240
#define PJ_BUF    20480
#define PJ_PARAMS 40960     // s_mean[128], s_rstd[128], sG[128], sT[128]
#define PJ_SMEM   43008

// ---------------- scratch (static device globals; no allocation) ----------------
__device__ __half g_K[MROWS*DD];    // 64 MB, fp16
__device__ __half g_V[MROWS*DD];    // 64 MB, fp16
__device__ float g_q[BB*SS*DD];
__device__ float g_part[BB*NCHUNK*PART_STRIDE];
__device__ __half g_WbH[128*256];   // fp16 g-scaled weights, row-major [n][c]
__device__ float g_Gn[128];         // G_n = sum_c g_c W_cn
__device__ float g_Tn[128];         // T_n = sum_c b_c W_cn

__device__ __forceinline__ float sigmoidf_(float x) { return 1.0f / (1.0f + __expf(-x)); }

__device__ __forceinline__ uint32_t smem_u32(const void* p) {
    uint32_t a;
    asm("{ .reg .u64 t; cvta.to.shared.u64 t, %1; cvt.u32.u64 %0, t; }" : "=r"(a) : "l"(p));
    return a;
}
__device__ __forceinline__ void mma16816(float* d, const uint32_t* a, const uint32_t* b) {
    asm volatile(
        "mma.sync.aligned.m16n8k16.row.col.f32.f16.f16.f32 "
        "{%0,%1,%2,%3}, {%4,%5,%6,%7}, {%8,%9}, {%0,%1,%2,%3};"
        : "+f"(d[0]), "+f"(d[1]), "+f"(d[2]), "+f"(d[3])
        : "r"(a[0]), "r"(a[1]), "r"(a[2]), "r"(a[3]), "r"(b[0]), "r"(b[1]));
}
__device__ __forceinline__ void ldsm_x4(uint32_t* r, uint32_t addr) {
    asm volatile("ldmatrix.sync.aligned.m8n8.x4.shared.b16 {%0,%1,%2,%3}, [%4];"
        : "=r"(r[0]), "=r"(r[1]), "=r"(r[2]), "=r"(r[3]) : "r"(addr));
}
__device__ __forceinline__ float4 h8tof4(uint2 u) {
    float2 a = __half22float2(*(__half2*)&u.x);
    float2 b = __half22float2(*(__half2*)&u.y);
    return make_float4(a.x, a.y, b.x, b.y);
}

// ---------------- kernel 0: fused slot init (out = mu) + iteration-0 q projection ----------------
__global__ void __launch_bounds__(256) initq_kernel(
    const float* __restrict__ mu_in, float* __restrict__ out,
    const float* __restrict__ qlg, const float* __restrict__ qlb,
    const float* __restrict__ Wq,
    const float* __restrict__ bqlg, const float* __restrict__ bqlb,
    const float* __restrict__ bWq)
{
    __shared__ float xs[8][64];
    const int tid = threadIdx.x, lane = tid & 31, ws = tid >> 5;
    const int wid = blockIdx.x * 8 + ws;          // 0..223 == b*7+m
    const int m = wid % SS;

    const float* x = mu_in + wid * DD;
    float x0 = x[lane], x1 = x[lane + 32];
    out[wid * DD + lane]      = x0;
    out[wid * DD + lane + 32] = x1;

    float s = x0 + x1, q = x0 * x0 + x1 * x1;
    #pragma unroll
    for (int o = 16; o; o >>= 1) {
        s += __shfl_xor_sync(0xffffffffu, s, o);
        q += __shfl_xor_sync(0xffffffffu, q, o);
    }
    float mu = s * (1.f / 64.f);
    float rs = rsqrtf(q * (1.f / 64.f) - mu * mu + LN_EPS);

    const float* lg = (m < 6) ? qlg : bqlg;
    const float* lb = (m < 6) ? qlb : bqlb;
    const float* W  = (m < 6) ? Wq  : bWq;

    xs[ws][lane]      = (x0 - mu) * rs * lg[lane]      + lb[lane];
    xs[ws][lane + 32] = (x1 - mu) * rs * lg[lane + 32] + lb[lane + 32];
    __syncwarp();

    float q0 = 0.f, q1 = 0.f;
    #pragma unroll
    for (int e = 0; e < 64; e++) {
        float xe = xs[ws][e];
        q0 += xe * W[e * 64 + lane];
        q1 += xe * W[e * 64 + lane + 32];
    }
    g_q[wid * DD + lane]      = q0;
    g_q[wid * DD + lane + 32] = q1;
}

// ---------------- kernel 0b: W' = g*[Wk|Wv]^T -> fp16 [n][c]; plus G/T column sums ----------------
__global__ void wsplit_kernel(const float* __restrict__ Wk, const float* __restrict__ Wv,
                              const float* __restrict__ lng, const float* __restrict__ lnb) {
    int idx = blockIdx.x * 256 + threadIdx.x;
    if (idx < 128 * 256) {
        int n = idx >> 8;
        int c = idx & 255;
        float w = (n < 64) ? Wk[c * 64 + n] : Wv[c * 64 + (n - 64)];
        g_WbH[n * 256 + c] = __float2half_rn(lng[c] * w);
    }
    if (blockIdx.x == 0 && threadIdx.x < 128) {
        int n = threadIdx.x;
        float G = 0.f, T = 0.f;
        #pragma unroll 4
        for (int c = 0; c < 256; c++) {
            float w = (n < 64) ? Wk[c * 64 + n] : Wv[c * 64 + (n - 64)];
            G += lng[c] * w;
            T += lnb[c] * w;
        }
        g_Gn[n] = G;
        g_Tn[n] = T;
    }
}

// ---------------- kernel 1: [K|V] projection on raw fp16 X; LN folded into epilogue ----------------
__global__ void __launch_bounds__(256, 2) proj_mma_kernel(const float* __restrict__ X)
{
    extern __shared__ char smem[];
    float* s_mean = (float*)(smem + PJ_PARAMS);
    float* s_rstd = (float*)(smem + PJ_PARAMS + 512);
    float* sG     = (float*)(smem + PJ_PARAMS + 1024);
    float* sT     = (float*)(smem + PJ_PARAMS + 1536);

    const int tid = threadIdx.x, wid = tid >> 5, lane = tid & 31;
    const int m0 = blockIdx.x * 128;
    const uint32_t sbase = smem_u32(smem);

    if (tid < 128) {
        sG[tid] = g_Gn[tid];
        sT[tid] = g_Tn[tid];
    }

    // loader roles
    const int r   = tid >> 1;
    const int seg = tid & 1;
    const float* xrow = X + (size_t)(m0 + r) * CC + seg * 16;
    const __half* wHrow = g_WbH + r * 256 + seg * 16;

    // mma roles
    const int mw = wid >> 1, nw = wid & 1;
    const int g  = lane >> 2, tg = lane & 3;
    const int mat = lane >> 3, rb = lane & 7;
    const uint32_t aoff = (uint32_t)((mw*32 + rb + (mat & 1)*8) * APITCH + (mat >> 1)*8) * 2;
    const uint32_t boff = (uint32_t)((nw*64 + rb) * APITCH + mat*8) * 2;

    float acc[2][8][4];
    #pragma unroll
    for (int mt = 0; mt < 2; mt++)
        #pragma unroll
        for (int nt = 0; nt < 8; nt++)
            #pragma unroll
            for (int e = 0; e < 4; e++) acc[mt][nt][e] = 0.f;

    float statS = 0.f, statQ = 0.f;   // per-thread LN partials (this thread's 128 cols)
    float4 xv[4];
    uint4 bvh[2];

    // prologue: load chunk0 regs, stage buf0 (+stats), load chunk1 regs
    #pragma unroll
    for (int i = 0; i < 4; i++) xv[i] = *(const float4*)(xrow + i * 4);
    bvh[0] = *(const uint4*)(wHrow);
    bvh[1] = *(const uint4*)(wHrow + 8);

    {   // stage chunk 0 -> buf 0
        char* Ah = smem;
        char* Bh = smem + PJ_B;
        uint32_t pk[8];
        #pragma unroll
        for (int i = 0; i < 4; i++) {
            statS += xv[i].x + xv[i].y + xv[i].z + xv[i].w;
            statQ += xv[i].x*xv[i].x + xv[i].y*xv[i].y + xv[i].z*xv[i].z + xv[i].w*xv[i].w;
            __half2 h01 = __float22half2_rn(make_float2(xv[i].x, xv[i].y));
            __half2 h23 = __float22half2_rn(make_float2(xv[i].z, xv[i].w));
            pk[i * 2]     = *(uint32_t*)&h01;
            pk[i * 2 + 1] = *(uint32_t*)&h23;
        }
        *(uint4*)(Ah + r * 80 + seg * 32)      = make_uint4(pk[0], pk[1], pk[2], pk[3]);
        *(uint4*)(Ah + r * 80 + seg * 32 + 16) = make_uint4(pk[4], pk[5], pk[6], pk[7]);
        *(uint4*)(Bh + r * 80 + seg * 32)      = bvh[0];
        *(uint4*)(Bh + r * 80 + seg * 32 + 16) = bvh[1];
    }
    #pragma unroll
    for (int i = 0; i < 4; i++) xv[i] = *(const float4*)(xrow + 32 + i * 4);
    bvh[0] = *(const uint4*)(wHrow + 32);
    bvh[1] = *(const uint4*)(wHrow + 40);
    __syncthreads();

    #pragma unroll 1
    for (int kc = 0; kc < 8; kc++) {
        const uint32_t bufo = (uint32_t)(kc & 1) * PJ_BUF;

        // ---- stage chunk kc+1 into the other buffer (+stats) ----
        if (kc < 7) {
            uint32_t nb = (uint32_t)((kc + 1) & 1) * PJ_BUF;
            char* Ah = smem + nb;
            char* Bh = smem + nb + PJ_B;
            uint32_t pk[8];
            #pragma unroll
            for (int i = 0; i < 4; i++) {
                statS += xv[i].x + xv[i].y + xv[i].z + xv[i].w;
                statQ += xv[i].x*xv[i].x + xv[i].y*xv[i].y + xv[i].z*xv[i].z + xv[i].w*xv[i].w;
                __half2 h01 = __float22half2_rn(make_float2(xv[i].x, xv[i].y));
                __half2 h23 = __float22half2_rn(make_float2(xv[i].z, xv[i].w));
                pk[i * 2]     = *(uint32_t*)&h01;
                pk[i * 2 + 1] = *(uint32_t*)&h23;
            }
            *(uint4*)(Ah + r * 80 + seg * 32)      = make_uint4(pk[0], pk[1], pk[2], pk[3]);
            *(uint4*)(Ah + r * 80 + seg * 32 + 16) = make_uint4(pk[4], pk[5], pk[6], pk[7]);
            *(uint4*)(Bh + r * 80 + seg * 32)      = bvh[0];
            *(uint4*)(Bh + r * 80 + seg * 32 + 16) = bvh[1];
        }
        // ---- prefetch chunk kc+2 from global ----
        if (kc < 6) {
            const float* xp = xrow + (kc + 2) * 32;
            #pragma unroll
            for (int i = 0; i < 4; i++) xv[i] = *(const float4*)(xp + i * 4);
            const __half* wh = wHrow + (kc + 2) * 32;
            bvh[0] = *(const uint4*)(wh);
            bvh[1] = *(const uint4*)(wh + 8);
        }

        // ---- MMA over current buffer via ldmatrix ----
        {
            const uint32_t aH = sbase + bufo + aoff;
            const uint32_t bH = sbase + bufo + PJ_B + boff;

            uint32_t ah[2][2][4];
            #pragma unroll
            for (int mt = 0; mt < 2; mt++)
                #pragma unroll
                for (int ks = 0; ks < 2; ks++)
                    ldsm_x4(ah[mt][ks], aH + mt * 1280 + ks * 32);
            #pragma unroll
            for (int nt = 0; nt < 8; nt++) {
                uint32_t bh[4];
                ldsm_x4(bh, bH + nt * 640);
                #pragma unroll
                for (int ks = 0; ks < 2; ks++)
                    #pragma unroll
                    for (int mt = 0; mt < 2; mt++)
                        mma16816(acc[mt][nt], ah[mt][ks], &bh[ks * 2]);
            }
        }
        __syncthreads();
    }

    // ---- finalize LN stats: combine the two per-row halves (partner lane) ----
    statS += __shfl_xor_sync(0xffffffffu, statS, 1);
    statQ += __shfl_xor_sync(0xffffffffu, statQ, 1);
    if (seg == 0) {
        float mu = statS * (1.f / 256.f);
        s_mean[r] = mu;
        s_rstd[r] = rsqrtf(statQ * (1.f / 256.f) - mu * mu + LN_EPS);
    }
    __syncthreads();

    // ---- epilogue: y = rs*(acc - mu*G) + T, stored as fp16 ----
    __half* dstbase = nw ? g_V : g_K;
    #pragma unroll
    for (int mt = 0; mt < 2; mt++) {
        int lr = mw * 32 + mt * 16 + g;
        float mu0 = s_mean[lr],     rs0 = s_rstd[lr];
        float mu1 = s_mean[lr + 8], rs1 = s_rstd[lr + 8];
        int row0 = m0 + lr;
        #pragma unroll
        for (int nt = 0; nt < 8; nt++) {
            int col = nw * 64 + nt * 8 + tg * 2;     // global n (for G/T)
            int coll = nt * 8 + tg * 2;              // col within K or V
            float G0 = sG[col], G1 = sG[col + 1];
            float T0 = sT[col], T1 = sT[col + 1];
            *(__half2*)(dstbase + (size_t)row0 * DD + coll) =
                __float22half2_rn(make_float2(rs0 * (acc[mt][nt][0] - mu0 * G0) + T0,
                                              rs0 * (acc[mt][nt][1] - mu0 * G1) + T1));
            *(__half2*)(dstbase + (size_t)(row0 + 8) * DD + coll) =
                __float22half2_rn(make_float2(rs1 * (acc[mt][nt][2] - mu1 * G0) + T0,
                                              rs1 * (acc[mt][nt][3] - mu1 * G1) + T1));
        }
    }
}

// ---------------- kernel 3: attention — fp16 K/V, 16 lanes/row, 2 rows/warp, 4-way n ILP ----------------
__global__ void __launch_bounds__(256, 2) attn_kernel(float* __restrict__ part)
{
    const int b = blockIdx.y;
    const int chunk = blockIdx.x;
    __shared__ float qs[SS * DD];
    __shared__ float Uw[8][PART_STRIDE];
    const int tid = threadIdx.x;
    for (int i = tid; i < SS * DD; i += 256) qs[i] = g_q[b * SS * DD + i];
    __syncthreads();

    const int lane = tid & 31, warp = tid >> 5;
    const int g = lane >> 4;   // row within pair
    const int j = lane & 15;   // d-slice owner (4 values)

    // hoist q fragments: lane owns d-slice [4j, 4j+3]
    float4 qreg[SS];
    #pragma unroll
    for (int m = 0; m < SS; m++)
        qreg[m] = *(const float4*)(qs + m * DD + j * 4);

    float Up[SS][4];
    #pragma unroll
    for (int m = 0; m < SS; m++)
        #pragma unroll
        for (int e = 0; e < 4; e++) Up[m][e] = 0.f;
    float cs[SS] = {0.f, 0.f, 0.f, 0.f, 0.f, 0.f, 0.f};

    const __half* Kb = g_K + (size_t)b * NN * DD;
    const __half* Vb = g_V + (size_t)b * NN * DD;
    const int base = chunk * CHUNK + warp * 2 + g;

    #pragma unroll 1
    for (int s = 0; s < CHUNK / 64; s++) {
        int n0 = base + s * 16;
        uint2 k2[4], v2[4];
        #pragma unroll
        for (int q = 0; q < 4; q++) {
            int n = n0 + q * (CHUNK / 4);
            k2[q] = __ldcs((const uint2*)(Kb + (size_t)n * DD) + j);
            v2[q] = __ldcs((const uint2*)(Vb + (size_t)n * DD) + j);
        }
        #pragma unroll
        for (int h = 0; h < 2; h++) {
            float4 ka = h8tof4(k2[h * 2]), kb = h8tof4(k2[h * 2 + 1]);
            float4 va = h8tof4(v2[h * 2]), vb = h8tof4(v2[h * 2 + 1]);
            float la[SS], lb_[SS];
            #pragma unroll
            for (int m = 0; m < SS; m++) {
                float pa = ka.x * qreg[m].x + ka.y * qreg[m].y + ka.z * qreg[m].z + ka.w * qreg[m].w;
                float pb = kb.x * qreg[m].x + kb.y * qreg[m].y + kb.z * qreg[m].z + kb.w * qreg[m].w;
                #pragma unroll
                for (int o = 1; o < 16; o <<= 1) {
                    pa += __shfl_xor_sync(0xffffffffu, pa, o);
                    pb += __shfl_xor_sync(0xffffffffu, pb, o);
                }
                la[m]  = pa * SCALE_ATTN;
                lb_[m] = pb * SCALE_ATTN;
            }
            float mxa = la[0], mxb = lb_[0];
            #pragma unroll
            for (int m = 1; m < SS; m++) { mxa = fmaxf(mxa, la[m]); mxb = fmaxf(mxb, lb_[m]); }
            float sa = 0.f, sb2 = 0.f;
            #pragma unroll
            for (int m = 0; m < SS; m++) {
                la[m]  = __expf(la[m] - mxa);  sa  += la[m];
                lb_[m] = __expf(lb_[m] - mxb); sb2 += lb_[m];
            }
            float inva = 1.0f / sa, invb = 1.0f / sb2;
            #pragma unroll
            for (int m = 0; m < SS; m++) {
                float aa = la[m] * inva + EPS_ATTN;
                float ab = lb_[m] * invb + EPS_ATTN;
                cs[m] += aa + ab;
                Up[m][0] += aa * va.x + ab * vb.x;
                Up[m][1] += aa * va.y + ab * vb.y;
                Up[m][2] += aa * va.z + ab * vb.z;
                Up[m][3] += aa * va.w + ab * vb.w;
            }
        }
    }

    #pragma unroll
    for (int m = 0; m < SS; m++) {
        #pragma unroll
        for (int e = 0; e < 4; e++) {
            float t = Up[m][e];
            t += __shfl_xor_sync(0xffffffffu, t, 16);
            Up[m][e] = t;
        }
        float c = cs[m];
        c += __shfl_xor_sync(0xffffffffu, c, 16);
        cs[m] = c;
    }
    if (lane < 16) {
        #pragma unroll
        for (int m = 0; m < SS; m++)
            #pragma unroll
            for (int e = 0; e < 4; e++)
                Uw[warp][m * DD + j * 4 + e] = Up[m][e];
    }
    if (lane == 0) {
        #pragma unroll
        for (int m = 0; m < SS; m++) Uw[warp][448 + m] = cs[m];
    }
    __syncthreads();

    float* dst = part + (size_t)(b * NCHUNK + chunk) * PART_STRIDE;
    for (int i = tid; i < 455; i += 256) {
        float acc = Uw[0][i];
        #pragma unroll
        for (int w = 1; w < 8; w++) acc += Uw[w][i];
        dst[i] = acc;
    }
}

// ---------------- kernel 4: slot update + fused next-iter q projection ----------------
__global__ void __launch_bounds__(128) update_kernel(
    float* __restrict__ slots,
    const float* __restrict__ Wih, const float* __restrict__ Whh,
    const float* __restrict__ bih, const float* __restrict__ bhh,
    const float* __restrict__ mlng, const float* __restrict__ mlnb,
    const float* __restrict__ mW1,  const float* __restrict__ mb1,
    const float* __restrict__ mW2,  const float* __restrict__ mb2,
    const float* __restrict__ bmlng, const float* __restrict__ bmlnb,
    const float* __restrict__ bmW1,  const float* __restrict__ bmb1,
    const float* __restrict__ bmW2,  const float* __restrict__ bmb2,
    const float* __restrict__ qlg, const float* __restrict__ qlb,
    const float* __restrict__ Wq,
    const float* __restrict__ bqlg, const float* __restrict__ bqlb,
    const float* __restrict__ bWq)
{
    const int b = blockIdx.y;
    const int s = blockIdx.x;
    const int t = threadIdx.x;

    __shared__ float us[64], hs[64], gi[192], gh[192], hn[64], xn[64], hid[128], fin[64], xq[64];
    __shared__ float red[2], red2[2];

    if (t < 64) {
        float ua = 0.f, ca = 0.f;
        #pragma unroll 1
        for (int c = 0; c < NCHUNK; c++) {
            const float* p = g_part + (size_t)(b * NCHUNK + c) * PART_STRIDE;
            ua += p[s * 64 + t];
            ca += p[448 + s];
        }
        us[t] = ua / ca;
        hs[t] = slots[(b * SS + s) * DD + t];
    }
    __syncthreads();

    for (int idx = t; idx < 384; idx += 128) {
        const bool isI = (idx < 192);
        const int oo = isI ? idx : (idx - 192);
        const float* W  = isI ? Wih : Whh;
        const float* xv = isI ? us : hs;
        float acc = isI ? bih[oo] : bhh[oo];
        #pragma unroll
        for (int e = 0; e < 64; e++) acc += xv[e] * W[oo * 64 + e];
        if (isI) gi[oo] = acc; else gh[oo] = acc;
    }
    __syncthreads();

    if (t < 64) {
        float r = sigmoidf_(gi[t] + gh[t]);
        float z = sigmoidf_(gi[64 + t] + gh[64 + t]);
        float n = tanhf(gi[128 + t] + r * gh[128 + t]);
        hn[t] = (1.0f - z) * n + z * hs[t];
    }
    __syncthreads();

    if (t < 32) {
        float a = hn[t], bv = hn[t + 32];
        float sm = a + bv, sq = a * a + bv * bv;
        #pragma unroll
        for (int o = 16; o; o >>= 1) {
            sm += __shfl_xor_sync(0xffffffffu, sm, o);
            sq += __shfl_xor_sync(0xffffffffu, sq, o);
        }
        if (t == 0) {
            float mu = sm * (1.f / 64.f);
            red[0] = mu;
            red[1] = rsqrtf(sq * (1.f / 64.f) - mu * mu + LN_EPS);
        }
    }
    __syncthreads();

    const float* lg = (s < 6) ? mlng : bmlng;
    const float* lb = (s < 6) ? mlnb : bmlnb;
    const float* W1 = (s < 6) ? mW1 : bmW1;
    const float* b1 = (s < 6) ? mb1 : bmb1;
    const float* W2 = (s < 6) ? mW2 : bmW2;
    const float* b2 = (s < 6) ? mb2 : bmb2;

    if (t < 64) xn[t] = (hn[t] - red[0]) * red[1] * lg[t] + lb[t];
    __syncthreads();

    {
        float h1 = b1[t];
        #pragma unroll
        for (int e = 0; e < 64; e++) h1 += xn[e] * W1[e * HH + t];
        hid[t] = fmaxf(h1, 0.f);
    }
    __syncthreads();

    if (t < 64) {
        float o = b2[t];
        #pragma unroll
        for (int jj = 0; jj < 128; jj++) o += hid[jj] * W2[jj * 64 + t];
        float fv = hn[t] + o;
        slots[(b * SS + s) * DD + t] = fv;
        fin[t] = fv;
    }
    __syncthreads();

    // ---- fused q projection for next iteration ----
    if (t < 32) {
        float a = fin[t], bv = fin[t + 32];
        float sm = a + bv, sq = a * a + bv * bv;
        #pragma unroll
        for (int o = 16; o; o >>= 1) {
            sm += __shfl_xor_sync(0xffffffffu, sm, o);
            sq += __shfl_xor_sync(0xffffffffu, sq, o);
        }
        if (t == 0) {
            float mu = sm * (1.f / 64.f);
            red2[0] = mu;
            red2[1] = rsqrtf(sq * (1.f / 64.f) - mu * mu + LN_EPS);
        }
    }
    __syncthreads();

    const float* qg = (s < 6) ? qlg : bqlg;
    const float* qb = (s < 6) ? qlb : bqlb;
    const float* qW = (s < 6) ? Wq  : bWq;

    if (t < 64) xq[t] = (fin[t] - red2[0]) * red2[1] * qg[t] + qb[t];
    __syncthreads();

    if (t < 64) {
        float qv = 0.f;
        #pragma unroll
        for (int e = 0; e < 64; e++) qv += xq[e] * qW[e * 64 + t];
        g_q[(b * SS + s) * DD + t] = qv;
    }
}

// ---------------- launcher ----------------
extern "C" void kernel_launch(void* const* d_in, const int* in_sizes, int n_in,
                              void* d_out, int out_size) {
    (void)in_sizes; (void)n_in; (void)out_size;
    const float* inputs   = (const float*)d_in[0];
    const float* slots_mu = (const float*)d_in[1];
    const float* ln_in_g  = (const float*)d_in[2];
    const float* ln_in_b  = (const float*)d_in[3];
    const float* Wk       = (const float*)d_in[4];
    const float* Wv       = (const float*)d_in[5];
    const float* q_ln_g   = (const float*)d_in[6];
    const float* q_ln_b   = (const float*)d_in[7];
    const float* Wq       = (const float*)d_in[8];
    const float* bq_ln_g  = (const float*)d_in[9];
    const float* bq_ln_b  = (const float*)d_in[10];
    const float* bWq      = (const float*)d_in[11];
    const float* gWih     = (const float*)d_in[12];
    const float* gWhh     = (const float*)d_in[13];
    const float* gbih     = (const float*)d_in[14];
    const float* gbhh     = (const float*)d_in[15];
    const float* mlng     = (const float*)d_in[16];
    const float* mlnb     = (const float*)d_in[17];
    const float* mW1      = (const float*)d_in[18];
    const float* mb1      = (const float*)d_in[19];
    const float* mW2      = (const float*)d_in[20];
    const float* mb2      = (const float*)d_in[21];
    const float* bmlng    = (const float*)d_in[22];
    const float* bmlnb    = (const float*)d_in[23];
    const float* bmW1     = (const float*)d_in[24];
    const float* bmb1     = (const float*)d_in[25];
    const float* bmW2     = (const float*)d_in[26];
    const float* bmb2     = (const float*)d_in[27];
    float* out = (float*)d_out;

    float* part;
    cudaGetSymbolAddress((void**)&part, g_part);

    cudaFuncSetAttribute(proj_mma_kernel,
                         cudaFuncAttributeMaxDynamicSharedMemorySize, PJ_SMEM);

    // order places attn_kernel at launch index 3 for the ncu fixed-index capture
    initq_kernel<<<28, 256>>>(slots_mu, out, q_ln_g, q_ln_b, Wq, bq_ln_g, bq_ln_b, bWq);
    wsplit_kernel<<<128, 256>>>(Wk, Wv, ln_in_g, ln_in_b);
    proj_mma_kernel<<<MROWS / 128, 256, PJ_SMEM>>>(inputs);

    for (int it = 0; it < 3; it++) {
        attn_kernel<<<dim3(NCHUNK, BB), 256>>>(part);
        update_kernel<<<dim3(SS, BB), 128>>>(out, gWih, gWhh, gbih, gbhh,
                                             mlng, mlnb, mW1, mb1, mW2, mb2,
                                             bmlng, bmlnb, bmW1, bmb1, bmW2, bmb2,
                                             q_ln_g, q_ln_b, Wq, bq_ln_g, bq_ln_b, bWq);
    }
}

// round 16
// speedup vs baseline: 1.4568x; 1.2375x over previous
#include <cuda_runtime.h>
#include <cuda_fp16.h>
#include <cstdint>

#define BB 32
#define NN 16384
#define CC 256
#define DD 64
#define SS 7
#define HH 128
#define MROWS (BB*NN)
#define SCALE_ATTN 0.125f
#define EPS_ATTN 1e-6f
#define LN_EPS 1e-5f
#define NCHUNK 16
#define CHUNK (NN/NCHUNK)
#define PART_STRIDE 456
#define APITCH 40
#define VPITCH 72   // halves; 144B rows -> conflict-free ldmatrix

#define PJ_B      10240
#define PJ_BUF    20480
#define PJ_PARAMS 40960
#define PJ_SMEM   43008

// ---------------- scratch (static device globals; no allocation) ----------------
__device__ __half g_K[MROWS*DD];    // 64 MB, fp16
__device__ __half g_V[MROWS*DD];    // 64 MB, fp16
__device__ float g_q[BB*SS*DD];
__device__ float g_part[BB*NCHUNK*PART_STRIDE];
__device__ __half g_WbH[128*256];
__device__ float g_Gn[128];
__device__ float g_Tn[128];

__device__ __forceinline__ float sigmoidf_(float x) { return 1.0f / (1.0f + __expf(-x)); }

__device__ __forceinline__ uint32_t smem_u32(const void* p) {
    uint32_t a;
    asm("{ .reg .u64 t; cvta.to.shared.u64 t, %1; cvt.u32.u64 %0, t; }" : "=r"(a) : "l"(p));
    return a;
}
__device__ __forceinline__ void mma16816(float* d, const uint32_t* a, const uint32_t* b) {
    asm volatile(
        "mma.sync.aligned.m16n8k16.row.col.f32.f16.f16.f32 "
        "{%0,%1,%2,%3}, {%4,%5,%6,%7}, {%8,%9}, {%0,%1,%2,%3};"
        : "+f"(d[0]), "+f"(d[1]), "+f"(d[2]), "+f"(d[3])
        : "r"(a[0]), "r"(a[1]), "r"(a[2]), "r"(a[3]), "r"(b[0]), "r"(b[1]));
}
__device__ __forceinline__ void ldsm_x4(uint32_t* r, uint32_t addr) {
    asm volatile("ldmatrix.sync.aligned.m8n8.x4.shared.b16 {%0,%1,%2,%3}, [%4];"
        : "=r"(r[0]), "=r"(r[1]), "=r"(r[2]), "=r"(r[3]) : "r"(addr));
}
__device__ __forceinline__ void ldsm_x4_t(uint32_t* r, uint32_t addr) {
    asm volatile("ldmatrix.sync.aligned.m8n8.x4.trans.shared.b16 {%0,%1,%2,%3}, [%4];"
        : "=r"(r[0]), "=r"(r[1]), "=r"(r[2]), "=r"(r[3]) : "r"(addr));
}

// ---------------- kernel 0: fused slot init (out = mu) + iteration-0 q projection ----------------
__global__ void __launch_bounds__(256) initq_kernel(
    const float* __restrict__ mu_in, float* __restrict__ out,
    const float* __restrict__ qlg, const float* __restrict__ qlb,
    const float* __restrict__ Wq,
    const float* __restrict__ bqlg, const float* __restrict__ bqlb,
    const float* __restrict__ bWq)
{
    __shared__ float xs[8][64];
    const int tid = threadIdx.x, lane = tid & 31, ws = tid >> 5;
    const int wid = blockIdx.x * 8 + ws;
    const int m = wid % SS;

    const float* x = mu_in + wid * DD;
    float x0 = x[lane], x1 = x[lane + 32];
    out[wid * DD + lane]      = x0;
    out[wid * DD + lane + 32] = x1;

    float s = x0 + x1, q = x0 * x0 + x1 * x1;
    #pragma unroll
    for (int o = 16; o; o >>= 1) {
        s += __shfl_xor_sync(0xffffffffu, s, o);
        q += __shfl_xor_sync(0xffffffffu, q, o);
    }
    float mu = s * (1.f / 64.f);
    float rs = rsqrtf(q * (1.f / 64.f) - mu * mu + LN_EPS);

    const float* lg = (m < 6) ? qlg : bqlg;
    const float* lb = (m < 6) ? qlb : bqlb;
    const float* W  = (m < 6) ? Wq  : bWq;

    xs[ws][lane]      = (x0 - mu) * rs * lg[lane]      + lb[lane];
    xs[ws][lane + 32] = (x1 - mu) * rs * lg[lane + 32] + lb[lane + 32];
    __syncwarp();

    float q0 = 0.f, q1 = 0.f;
    #pragma unroll
    for (int e = 0; e < 64; e++) {
        float xe = xs[ws][e];
        q0 += xe * W[e * 64 + lane];
        q1 += xe * W[e * 64 + lane + 32];
    }
    g_q[wid * DD + lane]      = q0;
    g_q[wid * DD + lane + 32] = q1;
}

// ---------------- kernel 0b: W' = g*[Wk|Wv]^T -> fp16 [n][c]; plus G/T column sums ----------------
__global__ void wsplit_kernel(const float* __restrict__ Wk, const float* __restrict__ Wv,
                              const float* __restrict__ lng, const float* __restrict__ lnb) {
    int idx = blockIdx.x * 256 + threadIdx.x;
    if (idx < 128 * 256) {
        int n = idx >> 8;
        int c = idx & 255;
        float w = (n < 64) ? Wk[c * 64 + n] : Wv[c * 64 + (n - 64)];
        g_WbH[n * 256 + c] = __float2half_rn(lng[c] * w);
    }
    if (blockIdx.x == 0 && threadIdx.x < 128) {
        int n = threadIdx.x;
        float G = 0.f, T = 0.f;
        #pragma unroll 4
        for (int c = 0; c < 256; c++) {
            float w = (n < 64) ? Wk[c * 64 + n] : Wv[c * 64 + (n - 64)];
            G += lng[c] * w;
            T += lnb[c] * w;
        }
        g_Gn[n] = G;
        g_Tn[n] = T;
    }
}

// ---------------- kernel 1: [K|V] projection on raw fp16 X; LN folded into epilogue ----------------
__global__ void __launch_bounds__(256, 2) proj_mma_kernel(const float* __restrict__ X)
{
    extern __shared__ char smem[];
    float* s_mean = (float*)(smem + PJ_PARAMS);
    float* s_rstd = (float*)(smem + PJ_PARAMS + 512);
    float* sG     = (float*)(smem + PJ_PARAMS + 1024);
    float* sT     = (float*)(smem + PJ_PARAMS + 1536);

    const int tid = threadIdx.x, wid = tid >> 5, lane = tid & 31;
    const int m0 = blockIdx.x * 128;
    const uint32_t sbase = smem_u32(smem);

    if (tid < 128) {
        sG[tid] = g_Gn[tid];
        sT[tid] = g_Tn[tid];
    }

    const int r   = tid >> 1;
    const int seg = tid & 1;
    const float* xrow = X + (size_t)(m0 + r) * CC + seg * 16;
    const __half* wHrow = g_WbH + r * 256 + seg * 16;

    const int mw = wid >> 1, nw = wid & 1;
    const int g  = lane >> 2, tg = lane & 3;
    const int mat = lane >> 3, rb = lane & 7;
    const uint32_t aoff = (uint32_t)((mw*32 + rb + (mat & 1)*8) * APITCH + (mat >> 1)*8) * 2;
    const uint32_t boff = (uint32_t)((nw*64 + rb) * APITCH + mat*8) * 2;

    float acc[2][8][4];
    #pragma unroll
    for (int mt = 0; mt < 2; mt++)
        #pragma unroll
        for (int nt = 0; nt < 8; nt++)
            #pragma unroll
            for (int e = 0; e < 4; e++) acc[mt][nt][e] = 0.f;

    float statS = 0.f, statQ = 0.f;
    float4 xv[4];
    uint4 bvh[2];

    #pragma unroll
    for (int i = 0; i < 4; i++) xv[i] = *(const float4*)(xrow + i * 4);
    bvh[0] = *(const uint4*)(wHrow);
    bvh[1] = *(const uint4*)(wHrow + 8);

    {
        char* Ah = smem;
        char* Bh = smem + PJ_B;
        uint32_t pk[8];
        #pragma unroll
        for (int i = 0; i < 4; i++) {
            statS += xv[i].x + xv[i].y + xv[i].z + xv[i].w;
            statQ += xv[i].x*xv[i].x + xv[i].y*xv[i].y + xv[i].z*xv[i].z + xv[i].w*xv[i].w;
            __half2 h01 = __float22half2_rn(make_float2(xv[i].x, xv[i].y));
            __half2 h23 = __float22half2_rn(make_float2(xv[i].z, xv[i].w));
            pk[i * 2]     = *(uint32_t*)&h01;
            pk[i * 2 + 1] = *(uint32_t*)&h23;
        }
        *(uint4*)(Ah + r * 80 + seg * 32)      = make_uint4(pk[0], pk[1], pk[2], pk[3]);
        *(uint4*)(Ah + r * 80 + seg * 32 + 16) = make_uint4(pk[4], pk[5], pk[6], pk[7]);
        *(uint4*)(Bh + r * 80 + seg * 32)      = bvh[0];
        *(uint4*)(Bh + r * 80 + seg * 32 + 16) = bvh[1];
    }
    #pragma unroll
    for (int i = 0; i < 4; i++) xv[i] = *(const float4*)(xrow + 32 + i * 4);
    bvh[0] = *(const uint4*)(wHrow + 32);
    bvh[1] = *(const uint4*)(wHrow + 40);
    __syncthreads();

    #pragma unroll 1
    for (int kc = 0; kc < 8; kc++) {
        const uint32_t bufo = (uint32_t)(kc & 1) * PJ_BUF;

        if (kc < 7) {
            uint32_t nb = (uint32_t)((kc + 1) & 1) * PJ_BUF;
            char* Ah = smem + nb;
            char* Bh = smem + nb + PJ_B;
            uint32_t pk[8];
            #pragma unroll
            for (int i = 0; i < 4; i++) {
                statS += xv[i].x + xv[i].y + xv[i].z + xv[i].w;
                statQ += xv[i].x*xv[i].x + xv[i].y*xv[i].y + xv[i].z*xv[i].z + xv[i].w*xv[i].w;
                __half2 h01 = __float22half2_rn(make_float2(xv[i].x, xv[i].y));
                __half2 h23 = __float22half2_rn(make_float2(xv[i].z, xv[i].w));
                pk[i * 2]     = *(uint32_t*)&h01;
                pk[i * 2 + 1] = *(uint32_t*)&h23;
            }
            *(uint4*)(Ah + r * 80 + seg * 32)      = make_uint4(pk[0], pk[1], pk[2], pk[3]);
            *(uint4*)(Ah + r * 80 + seg * 32 + 16) = make_uint4(pk[4], pk[5], pk[6], pk[7]);
            *(uint4*)(Bh + r * 80 + seg * 32)      = bvh[0];
            *(uint4*)(Bh + r * 80 + seg * 32 + 16) = bvh[1];
        }
        if (kc < 6) {
            const float* xp = xrow + (kc + 2) * 32;
            #pragma unroll
            for (int i = 0; i < 4; i++) xv[i] = *(const float4*)(xp + i * 4);
            const __half* wh = wHrow + (kc + 2) * 32;
            bvh[0] = *(const uint4*)(wh);
            bvh[1] = *(const uint4*)(wh + 8);
        }

        {
            const uint32_t aH = sbase + bufo + aoff;
            const uint32_t bH = sbase + bufo + PJ_B + boff;

            uint32_t ah[2][2][4];
            #pragma unroll
            for (int mt = 0; mt < 2; mt++)
                #pragma unroll
                for (int ks = 0; ks < 2; ks++)
                    ldsm_x4(ah[mt][ks], aH + mt * 1280 + ks * 32);
            #pragma unroll
            for (int nt = 0; nt < 8; nt++) {
                uint32_t bh[4];
                ldsm_x4(bh, bH + nt * 640);
                #pragma unroll
                for (int ks = 0; ks < 2; ks++)
                    #pragma unroll
                    for (int mt = 0; mt < 2; mt++)
                        mma16816(acc[mt][nt], ah[mt][ks], &bh[ks * 2]);
            }
        }
        __syncthreads();
    }

    statS += __shfl_xor_sync(0xffffffffu, statS, 1);
    statQ += __shfl_xor_sync(0xffffffffu, statQ, 1);
    if (seg == 0) {
        float mu = statS * (1.f / 256.f);
        s_mean[r] = mu;
        s_rstd[r] = rsqrtf(statQ * (1.f / 256.f) - mu * mu + LN_EPS);
    }
    __syncthreads();

    __half* dstbase = nw ? g_V : g_K;
    #pragma unroll
    for (int mt = 0; mt < 2; mt++) {
        int lr = mw * 32 + mt * 16 + g;
        float mu0 = s_mean[lr],     rs0 = s_rstd[lr];
        float mu1 = s_mean[lr + 8], rs1 = s_rstd[lr + 8];
        int row0 = m0 + lr;
        #pragma unroll
        for (int nt = 0; nt < 8; nt++) {
            int col = nw * 64 + nt * 8 + tg * 2;
            int coll = nt * 8 + tg * 2;
            float G0 = sG[col], G1 = sG[col + 1];
            float T0 = sT[col], T1 = sT[col + 1];
            *(__half2*)(dstbase + (size_t)row0 * DD + coll) =
                __float22half2_rn(make_float2(rs0 * (acc[mt][nt][0] - mu0 * G0) + T0,
                                              rs0 * (acc[mt][nt][1] - mu0 * G1) + T1));
            *(__half2*)(dstbase + (size_t)(row0 + 8) * DD + coll) =
                __float22half2_rn(make_float2(rs1 * (acc[mt][nt][2] - mu1 * G0) + T0,
                                              rs1 * (acc[mt][nt][3] - mu1 * G1) + T1));
        }
    }
}

// ---------------- kernel 3: tensor-core attention ----------------
// logits^T = Q(7pad16 x 64) @ K^T per 16-row tile; prob frag == A-frag of U-mma (no transpose)
__global__ void __launch_bounds__(256, 2) attn_kernel(float* __restrict__ part)
{
    const int b = blockIdx.y;
    const int chunk = blockIdx.x;
    __shared__ float qs[SS * DD];
    __shared__ float Uw[8][PART_STRIDE];
    __shared__ __half Vsm[8][16 * VPITCH];

    const int tid = threadIdx.x;
    for (int i = tid; i < SS * DD; i += 256) qs[i] = g_q[b * SS * DD + i];
    __syncthreads();

    const int lane = tid & 31, warp = tid >> 5;
    const int g = lane >> 2, tg = lane & 3;
    const uint32_t z = 0;

    // Q A-fragments (M=16 padded slots, K=64 in 4 chunks): a0=q0[kc], a2=q2[kc], a1=a3=0
    uint32_t q0[4], q2[4];
    #pragma unroll
    for (int kc = 0; kc < 4; kc++) {
        if (g < 7) {
            const float* qr = qs + g * DD + kc * 16 + tg * 2;
            __half2 h0 = __float22half2_rn(make_float2(qr[0], qr[1]));
            __half2 h2 = __float22half2_rn(make_float2(qr[8], qr[9]));
            q0[kc] = *(uint32_t*)&h0;
            q2[kc] = *(uint32_t*)&h2;
        } else { q0[kc] = 0; q2[kc] = 0; }
    }

    float Uacc[8][4];
    #pragma unroll
    for (int j = 0; j < 8; j++)
        #pragma unroll
        for (int e = 0; e < 4; e++) Uacc[j][e] = 0.f;
    float csl = 0.f;

    const __half* Kb = g_K + (size_t)b * NN * DD;
    const __half* Vb = g_V + (size_t)b * NN * DD;
    __half* vs = &Vsm[warp][0];
    const uint32_t vsb = smem_u32(vs);
    // ldmatrix.trans per-lane address (halves): row ((lane>>3)&1)*8 + (lane&7), colbase (lane>>4)*8
    const uint32_t vls = vsb + (((((lane >> 3) & 1) * 8 + (lane & 7)) * VPITCH + (lane >> 4) * 8) << 1);
    const int base = chunk * CHUNK + warp * (CHUNK / 8);

    #pragma unroll 1
    for (int s = 0; s < CHUNK / 128; s++) {
        const int n0 = base + s * 16;

        // V tile load (early, latency hidden by logits/softmax)
        uint4 vreg[4];
        #pragma unroll
        for (int i = 0; i < 4; i++) {
            int idx = i * 32 + lane;
            vreg[i] = __ldcs((const uint4*)(Vb + (size_t)(n0 + (idx >> 3)) * DD) + (idx & 7));
        }

        // K B-fragments direct from global: kb[ng][kc][h] = {K[n0+ng*8+g][16kc+8h+2tg], +1}
        uint32_t kb[2][4][2];
        #pragma unroll
        for (int ng = 0; ng < 2; ng++) {
            const uint32_t* kr = (const uint32_t*)(Kb + (size_t)(n0 + ng * 8 + g) * DD) + tg;
            #pragma unroll
            for (int kc = 0; kc < 4; kc++) {
                kb[ng][kc][0] = __ldcs(kr + kc * 8);
                kb[ng][kc][1] = __ldcs(kr + kc * 8 + 4);
            }
        }

        // logits^T: D[slot][krow] for 2 n-groups
        float D0[4] = {0.f, 0.f, 0.f, 0.f};
        float D1[4] = {0.f, 0.f, 0.f, 0.f};
        #pragma unroll
        for (int kc = 0; kc < 4; kc++) {
            uint32_t A[4] = {q0[kc], z, q2[kc], z};
            mma16816(D0, A, kb[0][kc]);
            mma16816(D1, A, kb[1][kc]);
        }

        // softmax over slots (column direction: reduce across g via xor 4,8,16)
        float l00 = D0[0] * SCALE_ATTN, l01 = D0[1] * SCALE_ATTN;
        float l10 = D1[0] * SCALE_ATTN, l11 = D1[1] * SCALE_ATTN;
        if (g == 7) { l00 = l01 = l10 = l11 = -1e30f; }
        float m00 = l00, m01 = l01, m10 = l10, m11 = l11;
        #pragma unroll
        for (int o = 4; o < 32; o <<= 1) {
            m00 = fmaxf(m00, __shfl_xor_sync(0xffffffffu, m00, o));
            m01 = fmaxf(m01, __shfl_xor_sync(0xffffffffu, m01, o));
            m10 = fmaxf(m10, __shfl_xor_sync(0xffffffffu, m10, o));
            m11 = fmaxf(m11, __shfl_xor_sync(0xffffffffu, m11, o));
        }
        float e00 = __expf(l00 - m00), e01 = __expf(l01 - m01);
        float e10 = __expf(l10 - m10), e11 = __expf(l11 - m11);
        float s00 = e00, s01 = e01, s10 = e10, s11 = e11;
        #pragma unroll
        for (int o = 4; o < 32; o <<= 1) {
            s00 += __shfl_xor_sync(0xffffffffu, s00, o);
            s01 += __shfl_xor_sync(0xffffffffu, s01, o);
            s10 += __shfl_xor_sync(0xffffffffu, s10, o);
            s11 += __shfl_xor_sync(0xffffffffu, s11, o);
        }
        float p00 = e00 / s00 + EPS_ATTN, p01 = e01 / s01 + EPS_ATTN;
        float p10 = e10 / s10 + EPS_ATTN, p11 = e11 / s11 + EPS_ATTN;
        csl += p00 + p01 + p10 + p11;
        __half2 hpa = __float22half2_rn(make_float2(p00, p01));
        __half2 hpc = __float22half2_rn(make_float2(p10, p11));
        uint32_t pa0 = *(uint32_t*)&hpa;
        uint32_t pa2 = *(uint32_t*)&hpc;

        // stage V into smem (pitch 72 halves)
        #pragma unroll
        for (int i = 0; i < 4; i++) {
            int idx = i * 32 + lane;
            *(uint4*)(vs + (idx >> 3) * VPITCH + (idx & 7) * 8) = vreg[i];
        }
        __syncwarp();

        // U-mma: A = {pa0, 0, pa2, 0}; B = V^T frags via ldmatrix.trans
        uint32_t A[4] = {pa0, z, pa2, z};
        #pragma unroll
        for (int t = 0; t < 4; t++) {
            uint32_t vb[4];
            ldsm_x4_t(vb, vls + (t << 5));
            mma16816(Uacc[2 * t],     A, &vb[0]);
            mma16816(Uacc[2 * t + 1], A, &vb[2]);
        }
        __syncwarp();
    }

    // write per-warp partials: lane(g,tg) owns U[g][16t+2tg(+1)] and [16t+8+2tg(+1)]
    if (g < 7) {
        #pragma unroll
        for (int t = 0; t < 4; t++) {
            Uw[warp][g * DD + 16 * t + 2 * tg]         = Uacc[2 * t][0];
            Uw[warp][g * DD + 16 * t + 2 * tg + 1]     = Uacc[2 * t][1];
            Uw[warp][g * DD + 16 * t + 8 + 2 * tg]     = Uacc[2 * t + 1][0];
            Uw[warp][g * DD + 16 * t + 8 + 2 * tg + 1] = Uacc[2 * t + 1][1];
        }
    }
    csl += __shfl_xor_sync(0xffffffffu, csl, 1);
    csl += __shfl_xor_sync(0xffffffffu, csl, 2);
    if (tg == 0 && g < 7) Uw[warp][448 + g] = csl;
    __syncthreads();

    float* dst = part + (size_t)(b * NCHUNK + chunk) * PART_STRIDE;
    for (int i = tid; i < 455; i += 256) {
        float acc = Uw[0][i];
        #pragma unroll
        for (int w = 1; w < 8; w++) acc += Uw[w][i];
        dst[i] = acc;
    }
}

// ---------------- kernel 4: slot update + fused next-iter q projection ----------------
__global__ void __launch_bounds__(128) update_kernel(
    float* __restrict__ slots,
    const float* __restrict__ Wih, const float* __restrict__ Whh,
    const float* __restrict__ bih, const float* __restrict__ bhh,
    const float* __restrict__ mlng, const float* __restrict__ mlnb,
    const float* __restrict__ mW1,  const float* __restrict__ mb1,
    const float* __restrict__ mW2,  const float* __restrict__ mb2,
    const float* __restrict__ bmlng, const float* __restrict__ bmlnb,
    const float* __restrict__ bmW1,  const float* __restrict__ bmb1,
    const float* __restrict__ bmW2,  const float* __restrict__ bmb2,
    const float* __restrict__ qlg, const float* __restrict__ qlb,
    const float* __restrict__ Wq,
    const float* __restrict__ bqlg, const float* __restrict__ bqlb,
    const float* __restrict__ bWq)
{
    const int b = blockIdx.y;
    const int s = blockIdx.x;
    const int t = threadIdx.x;

    __shared__ float us[64], hs[64], gi[192], gh[192], hn[64], xn[64], hid[128], fin[64], xq[64];
    __shared__ float red[2], red2[2];

    if (t < 64) {
        float ua = 0.f, ca = 0.f;
        #pragma unroll 1
        for (int c = 0; c < NCHUNK; c++) {
            const float* p = g_part + (size_t)(b * NCHUNK + c) * PART_STRIDE;
            ua += p[s * 64 + t];
            ca += p[448 + s];
        }
        us[t] = ua / ca;
        hs[t] = slots[(b * SS + s) * DD + t];
    }
    __syncthreads();

    for (int idx = t; idx < 384; idx += 128) {
        const bool isI = (idx < 192);
        const int oo = isI ? idx : (idx - 192);
        const float* W  = isI ? Wih : Whh;
        const float* xv = isI ? us : hs;
        float acc = isI ? bih[oo] : bhh[oo];
        #pragma unroll
        for (int e = 0; e < 64; e++) acc += xv[e] * W[oo * 64 + e];
        if (isI) gi[oo] = acc; else gh[oo] = acc;
    }
    __syncthreads();

    if (t < 64) {
        float r = sigmoidf_(gi[t] + gh[t]);
        float z = sigmoidf_(gi[64 + t] + gh[64 + t]);
        float n = tanhf(gi[128 + t] + r * gh[128 + t]);
        hn[t] = (1.0f - z) * n + z * hs[t];
    }
    __syncthreads();

    if (t < 32) {
        float a = hn[t], bv = hn[t + 32];
        float sm = a + bv, sq = a * a + bv * bv;
        #pragma unroll
        for (int o = 16; o; o >>= 1) {
            sm += __shfl_xor_sync(0xffffffffu, sm, o);
            sq += __shfl_xor_sync(0xffffffffu, sq, o);
        }
        if (t == 0) {
            float mu = sm * (1.f / 64.f);
            red[0] = mu;
            red[1] = rsqrtf(sq * (1.f / 64.f) - mu * mu + LN_EPS);
        }
    }
    __syncthreads();

    const float* lg = (s < 6) ? mlng : bmlng;
    const float* lb = (s < 6) ? mlnb : bmlnb;
    const float* W1 = (s < 6) ? mW1 : bmW1;
    const float* b1 = (s < 6) ? mb1 : bmb1;
    const float* W2 = (s < 6) ? mW2 : bmW2;
    const float* b2 = (s < 6) ? mb2 : bmb2;

    if (t < 64) xn[t] = (hn[t] - red[0]) * red[1] * lg[t] + lb[t];
    __syncthreads();

    {
        float h1 = b1[t];
        #pragma unroll
        for (int e = 0; e < 64; e++) h1 += xn[e] * W1[e * HH + t];
        hid[t] = fmaxf(h1, 0.f);
    }
    __syncthreads();

    if (t < 64) {
        float o = b2[t];
        #pragma unroll
        for (int jj = 0; jj < 128; jj++) o += hid[jj] * W2[jj * 64 + t];
        float fv = hn[t] + o;
        slots[(b * SS + s) * DD + t] = fv;
        fin[t] = fv;
    }
    __syncthreads();

    if (t < 32) {
        float a = fin[t], bv = fin[t + 32];
        float sm = a + bv, sq = a * a + bv * bv;
        #pragma unroll
        for (int o = 16; o; o >>= 1) {
            sm += __shfl_xor_sync(0xffffffffu, sm, o);
            sq += __shfl_xor_sync(0xffffffffu, sq, o);
        }
        if (t == 0) {
            float mu = sm * (1.f / 64.f);
            red2[0] = mu;
            red2[1] = rsqrtf(sq * (1.f / 64.f) - mu * mu + LN_EPS);
        }
    }
    __syncthreads();

    const float* qg = (s < 6) ? qlg : bqlg;
    const float* qb = (s < 6) ? qlb : bqlb;
    const float* qW = (s < 6) ? Wq  : bWq;

    if (t < 64) xq[t] = (fin[t] - red2[0]) * red2[1] * qg[t] + qb[t];
    __syncthreads();

    if (t < 64) {
        float qv = 0.f;
        #pragma unroll
        for (int e = 0; e < 64; e++) qv += xq[e] * qW[e * 64 + t];
        g_q[(b * SS + s) * DD + t] = qv;
    }
}

// ---------------- launcher ----------------
extern "C" void kernel_launch(void* const* d_in, const int* in_sizes, int n_in,
                              void* d_out, int out_size) {
    (void)in_sizes; (void)n_in; (void)out_size;
    const float* inputs   = (const float*)d_in[0];
    const float* slots_mu = (const float*)d_in[1];
    const float* ln_in_g  = (const float*)d_in[2];
    const float* ln_in_b  = (const float*)d_in[3];
    const float* Wk       = (const float*)d_in[4];
    const float* Wv       = (const float*)d_in[5];
    const float* q_ln_g   = (const float*)d_in[6];
    const float* q_ln_b   = (const float*)d_in[7];
    const float* Wq       = (const float*)d_in[8];
    const float* bq_ln_g  = (const float*)d_in[9];
    const float* bq_ln_b  = (const float*)d_in[10];
    const float* bWq      = (const float*)d_in[11];
    const float* gWih     = (const float*)d_in[12];
    const float* gWhh     = (const float*)d_in[13];
    const float* gbih     = (const float*)d_in[14];
    const float* gbhh     = (const float*)d_in[15];
    const float* mlng     = (const float*)d_in[16];
    const float* mlnb     = (const float*)d_in[17];
    const float* mW1      = (const float*)d_in[18];
    const float* mb1      = (const float*)d_in[19];
    const float* mW2      = (const float*)d_in[20];
    const float* mb2      = (const float*)d_in[21];
    const float* bmlng    = (const float*)d_in[22];
    const float* bmlnb    = (const float*)d_in[23];
    const float* bmW1     = (const float*)d_in[24];
    const float* bmb1     = (const float*)d_in[25];
    const float* bmW2     = (const float*)d_in[26];
    const float* bmb2     = (const float*)d_in[27];
    float* out = (float*)d_out;

    float* part;
    cudaGetSymbolAddress((void**)&part, g_part);

    cudaFuncSetAttribute(proj_mma_kernel,
                         cudaFuncAttributeMaxDynamicSharedMemorySize, PJ_SMEM);

    // order places attn_kernel at launch index 3 for the ncu fixed-index capture
    initq_kernel<<<28, 256>>>(slots_mu, out, q_ln_g, q_ln_b, Wq, bq_ln_g, bq_ln_b, bWq);
    wsplit_kernel<<<128, 256>>>(Wk, Wv, ln_in_g, ln_in_b);
    proj_mma_kernel<<<MROWS / 128, 256, PJ_SMEM>>>(inputs);

    for (int it = 0; it < 3; it++) {
        attn_kernel<<<dim3(NCHUNK, BB), 256>>>(part);
        update_kernel<<<dim3(SS, BB), 128>>>(out, gWih, gWhh, gbih, gbhh,
                                             mlng, mlnb, mW1, mb1, mW2, mb2,
                                             bmlng, bmlnb, bmW1, bmb1, bmW2, bmb2,
                                             q_ln_g, q_ln_b, Wq, bq_ln_g, bq_ln_b, bWq);
    }
}

// round 17
// speedup vs baseline: 1.5083x; 1.0354x over previous
#include <cuda_runtime.h>
#include <cuda_fp16.h>
#include <cstdint>

#define BB 32
#define NN 16384
#define CC 256
#define DD 64
#define SS 7
#define HH 128
#define MROWS (BB*NN)
#define SCALE_ATTN 0.125f
#define EPS_ATTN 1e-6f
#define LN_EPS 1e-5f
#define NCHUNK 16
#define CHUNK (NN/NCHUNK)
#define PART_STRIDE 456
#define APITCH 40
#define VPITCH 72   // halves; 144B rows -> conflict-free ldmatrix

#define PJ_B      10240
#define PJ_BUF    20480
#define PJ_PARAMS 40960
#define PJ_SMEM   43008

// ---------------- scratch (static device globals; no allocation) ----------------
__device__ __half g_K[MROWS*DD];    // 64 MB, fp16
__device__ __half g_V[MROWS*DD];    // 64 MB, fp16
__device__ float g_q[BB*SS*DD];
__device__ float g_part[BB*NCHUNK*PART_STRIDE];
__device__ __half g_WbH[128*256];
__device__ float g_Gn[128];
__device__ float g_Tn[128];

__device__ __forceinline__ float sigmoidf_(float x) { return 1.0f / (1.0f + __expf(-x)); }

__device__ __forceinline__ uint32_t smem_u32(const void* p) {
    uint32_t a;
    asm("{ .reg .u64 t; cvta.to.shared.u64 t, %1; cvt.u32.u64 %0, t; }" : "=r"(a) : "l"(p));
    return a;
}
__device__ __forceinline__ void mma16816(float* d, const uint32_t* a, const uint32_t* b) {
    asm volatile(
        "mma.sync.aligned.m16n8k16.row.col.f32.f16.f16.f32 "
        "{%0,%1,%2,%3}, {%4,%5,%6,%7}, {%8,%9}, {%0,%1,%2,%3};"
        : "+f"(d[0]), "+f"(d[1]), "+f"(d[2]), "+f"(d[3])
        : "r"(a[0]), "r"(a[1]), "r"(a[2]), "r"(a[3]), "r"(b[0]), "r"(b[1]));
}
__device__ __forceinline__ void ldsm_x4(uint32_t* r, uint32_t addr) {
    asm volatile("ldmatrix.sync.aligned.m8n8.x4.shared.b16 {%0,%1,%2,%3}, [%4];"
        : "=r"(r[0]), "=r"(r[1]), "=r"(r[2]), "=r"(r[3]) : "r"(addr));
}
__device__ __forceinline__ void ldsm_x4_t(uint32_t* r, uint32_t addr) {
    asm volatile("ldmatrix.sync.aligned.m8n8.x4.trans.shared.b16 {%0,%1,%2,%3}, [%4];"
        : "=r"(r[0]), "=r"(r[1]), "=r"(r[2]), "=r"(r[3]) : "r"(addr));
}

// ---------------- kernel 0: fused slot init (out = mu) + iteration-0 q projection ----------------
__global__ void __launch_bounds__(256) initq_kernel(
    const float* __restrict__ mu_in, float* __restrict__ out,
    const float* __restrict__ qlg, const float* __restrict__ qlb,
    const float* __restrict__ Wq,
    const float* __restrict__ bqlg, const float* __restrict__ bqlb,
    const float* __restrict__ bWq)
{
    __shared__ float xs[8][64];
    const int tid = threadIdx.x, lane = tid & 31, ws = tid >> 5;
    const int wid = blockIdx.x * 8 + ws;
    const int m = wid % SS;

    const float* x = mu_in + wid * DD;
    float x0 = x[lane], x1 = x[lane + 32];
    out[wid * DD + lane]      = x0;
    out[wid * DD + lane + 32] = x1;

    float s = x0 + x1, q = x0 * x0 + x1 * x1;
    #pragma unroll
    for (int o = 16; o; o >>= 1) {
        s += __shfl_xor_sync(0xffffffffu, s, o);
        q += __shfl_xor_sync(0xffffffffu, q, o);
    }
    float mu = s * (1.f / 64.f);
    float rs = rsqrtf(q * (1.f / 64.f) - mu * mu + LN_EPS);

    const float* lg = (m < 6) ? qlg : bqlg;
    const float* lb = (m < 6) ? qlb : bqlb;
    const float* W  = (m < 6) ? Wq  : bWq;

    xs[ws][lane]      = (x0 - mu) * rs * lg[lane]      + lb[lane];
    xs[ws][lane + 32] = (x1 - mu) * rs * lg[lane + 32] + lb[lane + 32];
    __syncwarp();

    float q0 = 0.f, q1 = 0.f;
    #pragma unroll
    for (int e = 0; e < 64; e++) {
        float xe = xs[ws][e];
        q0 += xe * W[e * 64 + lane];
        q1 += xe * W[e * 64 + lane + 32];
    }
    g_q[wid * DD + lane]      = q0;
    g_q[wid * DD + lane + 32] = q1;
}

// ---------------- kernel 0b: W' = g*[Wk|Wv]^T -> fp16 [n][c]; plus G/T column sums ----------------
__global__ void wsplit_kernel(const float* __restrict__ Wk, const float* __restrict__ Wv,
                              const float* __restrict__ lng, const float* __restrict__ lnb) {
    int idx = blockIdx.x * 256 + threadIdx.x;
    if (idx < 128 * 256) {
        int n = idx >> 8;
        int c = idx & 255;
        float w = (n < 64) ? Wk[c * 64 + n] : Wv[c * 64 + (n - 64)];
        g_WbH[n * 256 + c] = __float2half_rn(lng[c] * w);
    }
    if (blockIdx.x == 0 && threadIdx.x < 128) {
        int n = threadIdx.x;
        float G = 0.f, T = 0.f;
        #pragma unroll 4
        for (int c = 0; c < 256; c++) {
            float w = (n < 64) ? Wk[c * 64 + n] : Wv[c * 64 + (n - 64)];
            G += lng[c] * w;
            T += lnb[c] * w;
        }
        g_Gn[n] = G;
        g_Tn[n] = T;
    }
}

// ---------------- kernel 1: [K|V] projection on raw fp16 X; LN folded into epilogue ----------------
__global__ void __launch_bounds__(256, 2) proj_mma_kernel(const float* __restrict__ X)
{
    extern __shared__ char smem[];
    float* s_mean = (float*)(smem + PJ_PARAMS);
    float* s_rstd = (float*)(smem + PJ_PARAMS + 512);
    float* sG     = (float*)(smem + PJ_PARAMS + 1024);
    float* sT     = (float*)(smem + PJ_PARAMS + 1536);

    const int tid = threadIdx.x, wid = tid >> 5, lane = tid & 31;
    const int m0 = blockIdx.x * 128;
    const uint32_t sbase = smem_u32(smem);

    if (tid < 128) {
        sG[tid] = g_Gn[tid];
        sT[tid] = g_Tn[tid];
    }

    const int r   = tid >> 1;
    const int seg = tid & 1;
    const float* xrow = X + (size_t)(m0 + r) * CC + seg * 16;
    const __half* wHrow = g_WbH + r * 256 + seg * 16;

    const int mw = wid >> 1, nw = wid & 1;
    const int g  = lane >> 2, tg = lane & 3;
    const int mat = lane >> 3, rb = lane & 7;
    const uint32_t aoff = (uint32_t)((mw*32 + rb + (mat & 1)*8) * APITCH + (mat >> 1)*8) * 2;
    const uint32_t boff = (uint32_t)((nw*64 + rb) * APITCH + mat*8) * 2;

    float acc[2][8][4];
    #pragma unroll
    for (int mt = 0; mt < 2; mt++)
        #pragma unroll
        for (int nt = 0; nt < 8; nt++)
            #pragma unroll
            for (int e = 0; e < 4; e++) acc[mt][nt][e] = 0.f;

    float statS = 0.f, statQ = 0.f;
    float4 xv[4];
    uint4 bvh[2];

    #pragma unroll
    for (int i = 0; i < 4; i++) xv[i] = *(const float4*)(xrow + i * 4);
    bvh[0] = *(const uint4*)(wHrow);
    bvh[1] = *(const uint4*)(wHrow + 8);

    {
        char* Ah = smem;
        char* Bh = smem + PJ_B;
        uint32_t pk[8];
        #pragma unroll
        for (int i = 0; i < 4; i++) {
            statS += xv[i].x + xv[i].y + xv[i].z + xv[i].w;
            statQ += xv[i].x*xv[i].x + xv[i].y*xv[i].y + xv[i].z*xv[i].z + xv[i].w*xv[i].w;
            __half2 h01 = __float22half2_rn(make_float2(xv[i].x, xv[i].y));
            __half2 h23 = __float22half2_rn(make_float2(xv[i].z, xv[i].w));
            pk[i * 2]     = *(uint32_t*)&h01;
            pk[i * 2 + 1] = *(uint32_t*)&h23;
        }
        *(uint4*)(Ah + r * 80 + seg * 32)      = make_uint4(pk[0], pk[1], pk[2], pk[3]);
        *(uint4*)(Ah + r * 80 + seg * 32 + 16) = make_uint4(pk[4], pk[5], pk[6], pk[7]);
        *(uint4*)(Bh + r * 80 + seg * 32)      = bvh[0];
        *(uint4*)(Bh + r * 80 + seg * 32 + 16) = bvh[1];
    }
    #pragma unroll
    for (int i = 0; i < 4; i++) xv[i] = *(const float4*)(xrow + 32 + i * 4);
    bvh[0] = *(const uint4*)(wHrow + 32);
    bvh[1] = *(const uint4*)(wHrow + 40);
    __syncthreads();

    #pragma unroll 1
    for (int kc = 0; kc < 8; kc++) {
        const uint32_t bufo = (uint32_t)(kc & 1) * PJ_BUF;

        if (kc < 7) {
            uint32_t nb = (uint32_t)((kc + 1) & 1) * PJ_BUF;
            char* Ah = smem + nb;
            char* Bh = smem + nb + PJ_B;
            uint32_t pk[8];
            #pragma unroll
            for (int i = 0; i < 4; i++) {
                statS += xv[i].x + xv[i].y + xv[i].z + xv[i].w;
                statQ += xv[i].x*xv[i].x + xv[i].y*xv[i].y + xv[i].z*xv[i].z + xv[i].w*xv[i].w;
                __half2 h01 = __float22half2_rn(make_float2(xv[i].x, xv[i].y));
                __half2 h23 = __float22half2_rn(make_float2(xv[i].z, xv[i].w));
                pk[i * 2]     = *(uint32_t*)&h01;
                pk[i * 2 + 1] = *(uint32_t*)&h23;
            }
            *(uint4*)(Ah + r * 80 + seg * 32)      = make_uint4(pk[0], pk[1], pk[2], pk[3]);
            *(uint4*)(Ah + r * 80 + seg * 32 + 16) = make_uint4(pk[4], pk[5], pk[6], pk[7]);
            *(uint4*)(Bh + r * 80 + seg * 32)      = bvh[0];
            *(uint4*)(Bh + r * 80 + seg * 32 + 16) = bvh[1];
        }
        if (kc < 6) {
            const float* xp = xrow + (kc + 2) * 32;
            #pragma unroll
            for (int i = 0; i < 4; i++) xv[i] = *(const float4*)(xp + i * 4);
            const __half* wh = wHrow + (kc + 2) * 32;
            bvh[0] = *(const uint4*)(wh);
            bvh[1] = *(const uint4*)(wh + 8);
        }

        {
            const uint32_t aH = sbase + bufo + aoff;
            const uint32_t bH = sbase + bufo + PJ_B + boff;

            uint32_t ah[2][2][4];
            #pragma unroll
            for (int mt = 0; mt < 2; mt++)
                #pragma unroll
                for (int ks = 0; ks < 2; ks++)
                    ldsm_x4(ah[mt][ks], aH + mt * 1280 + ks * 32);
            #pragma unroll
            for (int nt = 0; nt < 8; nt++) {
                uint32_t bh[4];
                ldsm_x4(bh, bH + nt * 640);
                #pragma unroll
                for (int ks = 0; ks < 2; ks++)
                    #pragma unroll
                    for (int mt = 0; mt < 2; mt++)
                        mma16816(acc[mt][nt], ah[mt][ks], &bh[ks * 2]);
            }
        }
        __syncthreads();
    }

    statS += __shfl_xor_sync(0xffffffffu, statS, 1);
    statQ += __shfl_xor_sync(0xffffffffu, statQ, 1);
    if (seg == 0) {
        float mu = statS * (1.f / 256.f);
        s_mean[r] = mu;
        s_rstd[r] = rsqrtf(statQ * (1.f / 256.f) - mu * mu + LN_EPS);
    }
    __syncthreads();

    __half* dstbase = nw ? g_V : g_K;
    #pragma unroll
    for (int mt = 0; mt < 2; mt++) {
        int lr = mw * 32 + mt * 16 + g;
        float mu0 = s_mean[lr],     rs0 = s_rstd[lr];
        float mu1 = s_mean[lr + 8], rs1 = s_rstd[lr + 8];
        int row0 = m0 + lr;
        #pragma unroll
        for (int nt = 0; nt < 8; nt++) {
            int col = nw * 64 + nt * 8 + tg * 2;
            int coll = nt * 8 + tg * 2;
            float G0 = sG[col], G1 = sG[col + 1];
            float T0 = sT[col], T1 = sT[col + 1];
            *(__half2*)(dstbase + (size_t)row0 * DD + coll) =
                __float22half2_rn(make_float2(rs0 * (acc[mt][nt][0] - mu0 * G0) + T0,
                                              rs0 * (acc[mt][nt][1] - mu0 * G1) + T1));
            *(__half2*)(dstbase + (size_t)(row0 + 8) * DD + coll) =
                __float22half2_rn(make_float2(rs1 * (acc[mt][nt][2] - mu1 * G0) + T0,
                                              rs1 * (acc[mt][nt][3] - mu1 * G1) + T1));
        }
    }
}

// ---------------- kernel 3: tensor-core attention (K staged through smem + ldmatrix) ----------------
__global__ void __launch_bounds__(256, 2) attn_kernel(float* __restrict__ part)
{
    const int b = blockIdx.y;
    const int chunk = blockIdx.x;
    __shared__ float qs[SS * DD];
    __shared__ float Uw[8][PART_STRIDE];
    __shared__ __half Tsm[8][16 * VPITCH];   // per-warp tile buffer, reused for K then V

    const int tid = threadIdx.x;
    for (int i = tid; i < SS * DD; i += 256) qs[i] = g_q[b * SS * DD + i];
    __syncthreads();

    const int lane = tid & 31, warp = tid >> 5;
    const int g = lane >> 2, tg = lane & 3;
    const uint32_t z = 0;

    // Q A-fragments (M=16 padded slots, K=64 in 4 chunks)
    uint32_t q0[4], q2[4];
    #pragma unroll
    for (int kc = 0; kc < 4; kc++) {
        if (g < 7) {
            const float* qr = qs + g * DD + kc * 16 + tg * 2;
            __half2 h0 = __float22half2_rn(make_float2(qr[0], qr[1]));
            __half2 h2 = __float22half2_rn(make_float2(qr[8], qr[9]));
            q0[kc] = *(uint32_t*)&h0;
            q2[kc] = *(uint32_t*)&h2;
        } else { q0[kc] = 0; q2[kc] = 0; }
    }

    float Uacc[8][4];
    #pragma unroll
    for (int j = 0; j < 8; j++)
        #pragma unroll
        for (int e = 0; e < 4; e++) Uacc[j][e] = 0.f;
    float csl = 0.f;

    const __half* Kb = g_K + (size_t)b * NN * DD;
    const __half* Vb = g_V + (size_t)b * NN * DD;
    __half* ts = &Tsm[warp][0];
    const uint32_t tsb = smem_u32(ts);
    // staging store: lane handles rows (lane>>3) + 4i, 8-half column group (lane&7)
    const uint32_t stso = (uint32_t)(((lane >> 3) * VPITCH + (lane & 7) * 8) << 1);
    // ldsm (non-trans) K: matrix rows (lane&7), col group (lane>>3)*8, +ng rows, +h 32-half offset
    const uint32_t kls = tsb + (uint32_t)((((lane & 7) * VPITCH + (lane >> 3) * 8)) << 1);
    // ldsm (trans) V: rows ((lane>>3)&1)*8+(lane&7), colbase (lane>>4)*8
    const uint32_t vls = tsb + (uint32_t)((((((lane >> 3) & 1) * 8 + (lane & 7)) * VPITCH + (lane >> 4) * 8)) << 1);
    const int base = chunk * CHUNK + warp * (CHUNK / 8);

    #pragma unroll 1
    for (int s = 0; s < CHUNK / 128; s++) {
        const int n0 = base + s * 16;

        // coalesced tile loads: 4 x LDG.128 each for K and V
        uint4 kreg[4], vreg[4];
        #pragma unroll
        for (int i = 0; i < 4; i++) {
            int idx = i * 32 + lane;
            kreg[i] = __ldcs((const uint4*)(Kb + (size_t)(n0 + (idx >> 3)) * DD) + (idx & 7));
            vreg[i] = __ldcs((const uint4*)(Vb + (size_t)(n0 + (idx >> 3)) * DD) + (idx & 7));
        }

        // stage K, build B-fragments via ldmatrix
        #pragma unroll
        for (int i = 0; i < 4; i++)
            *(uint4*)((char*)ts + i * (4 * VPITCH * 2) + stso) = kreg[i];
        __syncwarp();
        uint32_t kfr[2][2][4];
        #pragma unroll
        for (int ng = 0; ng < 2; ng++)
            #pragma unroll
            for (int h = 0; h < 2; h++)
                ldsm_x4(kfr[ng][h], kls + ng * (8 * VPITCH * 2) + h * 64);
        __syncwarp();

        // logits^T: D[slot][krow] for 2 n-groups
        float D0[4] = {0.f, 0.f, 0.f, 0.f};
        float D1[4] = {0.f, 0.f, 0.f, 0.f};
        #pragma unroll
        for (int kc = 0; kc < 4; kc++) {
            uint32_t A[4] = {q0[kc], z, q2[kc], z};
            mma16816(D0, A, &kfr[0][kc >> 1][(kc & 1) * 2]);
            mma16816(D1, A, &kfr[1][kc >> 1][(kc & 1) * 2]);
        }

        // softmax over slots (reduce across g via xor 4,8,16)
        float l00 = D0[0] * SCALE_ATTN, l01 = D0[1] * SCALE_ATTN;
        float l10 = D1[0] * SCALE_ATTN, l11 = D1[1] * SCALE_ATTN;
        if (g == 7) { l00 = l01 = l10 = l11 = -1e30f; }
        float m00 = l00, m01 = l01, m10 = l10, m11 = l11;
        #pragma unroll
        for (int o = 4; o < 32; o <<= 1) {
            m00 = fmaxf(m00, __shfl_xor_sync(0xffffffffu, m00, o));
            m01 = fmaxf(m01, __shfl_xor_sync(0xffffffffu, m01, o));
            m10 = fmaxf(m10, __shfl_xor_sync(0xffffffffu, m10, o));
            m11 = fmaxf(m11, __shfl_xor_sync(0xffffffffu, m11, o));
        }
        float e00 = __expf(l00 - m00), e01 = __expf(l01 - m01);
        float e10 = __expf(l10 - m10), e11 = __expf(l11 - m11);
        float s00 = e00, s01 = e01, s10 = e10, s11 = e11;
        #pragma unroll
        for (int o = 4; o < 32; o <<= 1) {
            s00 += __shfl_xor_sync(0xffffffffu, s00, o);
            s01 += __shfl_xor_sync(0xffffffffu, s01, o);
            s10 += __shfl_xor_sync(0xffffffffu, s10, o);
            s11 += __shfl_xor_sync(0xffffffffu, s11, o);
        }
        float p00 = e00 / s00 + EPS_ATTN, p01 = e01 / s01 + EPS_ATTN;
        float p10 = e10 / s10 + EPS_ATTN, p11 = e11 / s11 + EPS_ATTN;
        csl += p00 + p01 + p10 + p11;
        __half2 hpa = __float22half2_rn(make_float2(p00, p01));
        __half2 hpc = __float22half2_rn(make_float2(p10, p11));
        uint32_t pa0 = *(uint32_t*)&hpa;
        uint32_t pa2 = *(uint32_t*)&hpc;

        // stage V (overwrites K tile; K frags already consumed)
        #pragma unroll
        for (int i = 0; i < 4; i++)
            *(uint4*)((char*)ts + i * (4 * VPITCH * 2) + stso) = vreg[i];
        __syncwarp();

        // U-mma: A = {pa0, 0, pa2, 0}; B = V^T frags via ldmatrix.trans
        uint32_t A[4] = {pa0, z, pa2, z};
        #pragma unroll
        for (int t = 0; t < 4; t++) {
            uint32_t vb[4];
            ldsm_x4_t(vb, vls + (t << 5));
            mma16816(Uacc[2 * t],     A, &vb[0]);
            mma16816(Uacc[2 * t + 1], A, &vb[2]);
        }
        __syncwarp();
    }

    // write per-warp partials
    if (g < 7) {
        #pragma unroll
        for (int t = 0; t < 4; t++) {
            Uw[warp][g * DD + 16 * t + 2 * tg]         = Uacc[2 * t][0];
            Uw[warp][g * DD + 16 * t + 2 * tg + 1]     = Uacc[2 * t][1];
            Uw[warp][g * DD + 16 * t + 8 + 2 * tg]     = Uacc[2 * t + 1][0];
            Uw[warp][g * DD + 16 * t + 8 + 2 * tg + 1] = Uacc[2 * t + 1][1];
        }
    }
    csl += __shfl_xor_sync(0xffffffffu, csl, 1);
    csl += __shfl_xor_sync(0xffffffffu, csl, 2);
    if (tg == 0 && g < 7) Uw[warp][448 + g] = csl;
    __syncthreads();

    float* dst = part + (size_t)(b * NCHUNK + chunk) * PART_STRIDE;
    for (int i = tid; i < 455; i += 256) {
        float acc = Uw[0][i];
        #pragma unroll
        for (int w = 1; w < 8; w++) acc += Uw[w][i];
        dst[i] = acc;
    }
}

// ---------------- kernel 4: slot update + fused next-iter q projection ----------------
__global__ void __launch_bounds__(128) update_kernel(
    float* __restrict__ slots,
    const float* __restrict__ Wih, const float* __restrict__ Whh,
    const float* __restrict__ bih, const float* __restrict__ bhh,
    const float* __restrict__ mlng, const float* __restrict__ mlnb,
    const float* __restrict__ mW1,  const float* __restrict__ mb1,
    const float* __restrict__ mW2,  const float* __restrict__ mb2,
    const float* __restrict__ bmlng, const float* __restrict__ bmlnb,
    const float* __restrict__ bmW1,  const float* __restrict__ bmb1,
    const float* __restrict__ bmW2,  const float* __restrict__ bmb2,
    const float* __restrict__ qlg, const float* __restrict__ qlb,
    const float* __restrict__ Wq,
    const float* __restrict__ bqlg, const float* __restrict__ bqlb,
    const float* __restrict__ bWq)
{
    const int b = blockIdx.y;
    const int s = blockIdx.x;
    const int t = threadIdx.x;

    __shared__ float us[64], hs[64], gi[192], gh[192], hn[64], xn[64], hid[128], fin[64], xq[64];
    __shared__ float red[2], red2[2];

    if (t < 64) {
        float ua = 0.f, ca = 0.f;
        #pragma unroll 1
        for (int c = 0; c < NCHUNK; c++) {
            const float* p = g_part + (size_t)(b * NCHUNK + c) * PART_STRIDE;
            ua += p[s * 64 + t];
            ca += p[448 + s];
        }
        us[t] = ua / ca;
        hs[t] = slots[(b * SS + s) * DD + t];
    }
    __syncthreads();

    for (int idx = t; idx < 384; idx += 128) {
        const bool isI = (idx < 192);
        const int oo = isI ? idx : (idx - 192);
        const float* W  = isI ? Wih : Whh;
        const float* xv = isI ? us : hs;
        float acc = isI ? bih[oo] : bhh[oo];
        #pragma unroll
        for (int e = 0; e < 64; e++) acc += xv[e] * W[oo * 64 + e];
        if (isI) gi[oo] = acc; else gh[oo] = acc;
    }
    __syncthreads();

    if (t < 64) {
        float r = sigmoidf_(gi[t] + gh[t]);
        float z = sigmoidf_(gi[64 + t] + gh[64 + t]);
        float n = tanhf(gi[128 + t] + r * gh[128 + t]);
        hn[t] = (1.0f - z) * n + z * hs[t];
    }
    __syncthreads();

    if (t < 32) {
        float a = hn[t], bv = hn[t + 32];
        float sm = a + bv, sq = a * a + bv * bv;
        #pragma unroll
        for (int o = 16; o; o >>= 1) {
            sm += __shfl_xor_sync(0xffffffffu, sm, o);
            sq += __shfl_xor_sync(0xffffffffu, sq, o);
        }
        if (t == 0) {
            float mu = sm * (1.f / 64.f);
            red[0] = mu;
            red[1] = rsqrtf(sq * (1.f / 64.f) - mu * mu + LN_EPS);
        }
    }
    __syncthreads();

    const float* lg = (s < 6) ? mlng : bmlng;
    const float* lb = (s < 6) ? mlnb : bmlnb;
    const float* W1 = (s < 6) ? mW1 : bmW1;
    const float* b1 = (s < 6) ? mb1 : bmb1;
    const float* W2 = (s < 6) ? mW2 : bmW2;
    const float* b2 = (s < 6) ? mb2 : bmb2;

    if (t < 64) xn[t] = (hn[t] - red[0]) * red[1] * lg[t] + lb[t];
    __syncthreads();

    {
        float h1 = b1[t];
        #pragma unroll
        for (int e = 0; e < 64; e++) h1 += xn[e] * W1[e * HH + t];
        hid[t] = fmaxf(h1, 0.f);
    }
    __syncthreads();

    if (t < 64) {
        float o = b2[t];
        #pragma unroll
        for (int jj = 0; jj < 128; jj++) o += hid[jj] * W2[jj * 64 + t];
        float fv = hn[t] + o;
        slots[(b * SS + s) * DD + t] = fv;
        fin[t] = fv;
    }
    __syncthreads();

    if (t < 32) {
        float a = fin[t], bv = fin[t + 32];
        float sm = a + bv, sq = a * a + bv * bv;
        #pragma unroll
        for (int o = 16; o; o >>= 1) {
            sm += __shfl_xor_sync(0xffffffffu, sm, o);
            sq += __shfl_xor_sync(0xffffffffu, sq, o);
        }
        if (t == 0) {
            float mu = sm * (1.f / 64.f);
            red2[0] = mu;
            red2[1] = rsqrtf(sq * (1.f / 64.f) - mu * mu + LN_EPS);
        }
    }
    __syncthreads();

    const float* qg = (s < 6) ? qlg : bqlg;
    const float* qb = (s < 6) ? qlb : bqlb;
    const float* qW = (s < 6) ? Wq  : bWq;

    if (t < 64) xq[t] = (fin[t] - red2[0]) * red2[1] * qg[t] + qb[t];
    __syncthreads();

    if (t < 64) {
        float qv = 0.f;
        #pragma unroll
        for (int e = 0; e < 64; e++) qv += xq[e] * qW[e * 64 + t];
        g_q[(b * SS + s) * DD + t] = qv;
    }
}

// ---------------- launcher ----------------
extern "C" void kernel_launch(void* const* d_in, const int* in_sizes, int n_in,
                              void* d_out, int out_size) {
    (void)in_sizes; (void)n_in; (void)out_size;
    const float* inputs   = (const float*)d_in[0];
    const float* slots_mu = (const float*)d_in[1];
    const float* ln_in_g  = (const float*)d_in[2];
    const float* ln_in_b  = (const float*)d_in[3];
    const float* Wk       = (const float*)d_in[4];
    const float* Wv       = (const float*)d_in[5];
    const float* q_ln_g   = (const float*)d_in[6];
    const float* q_ln_b   = (const float*)d_in[7];
    const float* Wq       = (const float*)d_in[8];
    const float* bq_ln_g  = (const float*)d_in[9];
    const float* bq_ln_b  = (const float*)d_in[10];
    const float* bWq      = (const float*)d_in[11];
    const float* gWih     = (const float*)d_in[12];
    const float* gWhh     = (const float*)d_in[13];
    const float* gbih     = (const float*)d_in[14];
    const float* gbhh     = (const float*)d_in[15];
    const float* mlng     = (const float*)d_in[16];
    const float* mlnb     = (const float*)d_in[17];
    const float* mW1      = (const float*)d_in[18];
    const float* mb1      = (const float*)d_in[19];
    const float* mW2      = (const float*)d_in[20];
    const float* mb2      = (const float*)d_in[21];
    const float* bmlng    = (const float*)d_in[22];
    const float* bmlnb    = (const float*)d_in[23];
    const float* bmW1     = (const float*)d_in[24];
    const float* bmb1     = (const float*)d_in[25];
    const float* bmW2     = (const float*)d_in[26];
    const float* bmb2     = (const float*)d_in[27];
    float* out = (float*)d_out;

    float* part;
    cudaGetSymbolAddress((void**)&part, g_part);

    cudaFuncSetAttribute(proj_mma_kernel,
                         cudaFuncAttributeMaxDynamicSharedMemorySize, PJ_SMEM);

    // order places attn_kernel at launch index 3 for the ncu fixed-index capture
    initq_kernel<<<28, 256>>>(slots_mu, out, q_ln_g, q_ln_b, Wq, bq_ln_g, bq_ln_b, bWq);
    wsplit_kernel<<<128, 256>>>(Wk, Wv, ln_in_g, ln_in_b);
    proj_mma_kernel<<<MROWS / 128, 256, PJ_SMEM>>>(inputs);

    for (int it = 0; it < 3; it++) {
        attn_kernel<<<dim3(NCHUNK, BB), 256>>>(part);
        update_kernel<<<dim3(SS, BB), 128>>>(out, gWih, gWhh, gbih, gbhh,
                                             mlng, mlnb, mW1, mb1, mW2, mb2,
                                             bmlng, bmlnb, bmW1, bmb1, bmW2, bmb2,
                                             q_ln_g, q_ln_b, Wq, bq_ln_g, bq_ln_b, bWq);
    }
}